// round 6
// baseline (speedup 1.0000x reference)
#include <cuda_runtime.h>
#include <cuda_bf16.h>
#include <math.h>
#include <stdint.h>

#define BB 64
#define TT 256
#define EE 300
#define UU 512
#define GG 2048
#define TBT (BB*TT)     /* 16384 rows per direction */
#define M2  (2*TBT)     /* 32768 total rows */

// ---------------- device scratch (static allocation only) ----------------
__device__ float g_z[(size_t)M2 * GG];            // [2][B][T][4U]
__device__ float g_hall1[(size_t)2 * TBT * UU];   // [2][B][T][U]
__device__ float g_hall2[(size_t)2 * TBT * UU];   // [2][B][T][U]
__device__ float g_enc[(size_t)TBT * UU];         // [B][T][U]
__device__ float g_scores[TBT];                   // [B][T]
__device__ float g_pooled[BB * UU];               // [B][U]
__device__ int   g_cnt[2 * TT];                   // per-dir per-step arrival counters
__device__ __nv_bfloat16 g_hbf[2 * 2 * BB * UU];  // [dir][parity][B][U] bf16 h

__device__ __forceinline__ float sigf(float x) { return 1.f / (1.f + __expf(-x)); }
__device__ __forceinline__ float ssf(float x)  { return x / (1.f + fabsf(x)); }

__device__ __forceinline__ float to_tf32(float x) {
    uint32_t u; asm("cvt.rna.tf32.f32 %0, %1;" : "=r"(u) : "f"(x));
    return __uint_as_float(u);
}
__device__ __forceinline__ uint32_t fu(float x) { return __float_as_uint(x); }

__device__ __forceinline__ void relAdd(int* p) {
    asm volatile("red.release.gpu.global.add.s32 [%0], 1;" :: "l"(p) : "memory");
}
__device__ __forceinline__ int acqLd(const int* p) {
    int v; asm volatile("ld.acquire.gpu.global.s32 %0, [%1];" : "=r"(v) : "l"(p) : "memory");
    return v;
}

#define MMA_TF32(d0,d1,d2,d3,a0,a1,a2,a3,b0,b1) \
    asm volatile("mma.sync.aligned.m16n8k8.row.col.f32.tf32.tf32.f32 " \
        "{%0,%1,%2,%3}, {%4,%5,%6,%7}, {%8,%9}, {%0,%1,%2,%3};" \
        : "+f"(d0), "+f"(d1), "+f"(d2), "+f"(d3) \
        : "r"(a0), "r"(a1), "r"(a2), "r"(a3), "r"(b0), "r"(b1))

#define MMA_BF16(d0,d1,d2,d3,a0,a1,a2,a3,b0,b1) \
    asm volatile("mma.sync.aligned.m16n8k16.row.col.f32.bf16.bf16.f32 " \
        "{%0,%1,%2,%3}, {%4,%5,%6,%7}, {%8,%9}, {%0,%1,%2,%3};" \
        : "+f"(d0), "+f"(d1), "+f"(d2), "+f"(d3) \
        : "r"(a0), "r"(a1), "r"(a2), "r"(a3), "r"(b0), "r"(b1))

// ================= big GEMM via tf32 mma: g_z = A @ Bmat + bias =================
__global__ __launch_bounds__(256) void gemm_mma(
    const int* __restrict__ ids, const float* __restrict__ emb,
    const float* __restrict__ Bbase, long Bstride,
    const float* __restrict__ biasBase, long biasStride,
    int K, int asel)
{
    __shared__ float As[128 * 36];
    __shared__ float Bs[32 * 72];
    __shared__ const float* rowp[128];

    const int m0 = blockIdx.x * 128;
    const int n0 = blockIdx.y * 64;
    const int d  = m0 / TBT;
    const float* Bmat = Bbase + (long)d * Bstride;
    const float* bias = biasBase + (long)d * biasStride;
    const int tid = threadIdx.x;

    if (tid < 128) {
        int m = m0 + tid;
        if (asel == 0) {
            int bt = m % TBT;
            int b = bt / TT, t = bt % TT;
            int tt = d ? (TT - 1 - t) : t;
            rowp[tid] = emb + (long)ids[b * TT + tt] * EE;
        } else {
            const float* hall = (asel == 1) ? g_hall1 : g_hall2;
            rowp[tid] = hall + (long)m * UU;
        }
    }
    __syncthreads();

    const int w = tid >> 5, lane = tid & 31;
    const int g = lane >> 2, t4 = lane & 3;
    const int mw = (w >> 1) * 32;
    const int nw = (w & 1) * 32;

    float acc[2][4][4];
    #pragma unroll
    for (int a = 0; a < 2; a++)
        #pragma unroll
        for (int b = 0; b < 4; b++)
            #pragma unroll
            for (int c = 0; c < 4; c++) acc[a][b][c] = 0.f;

    float4 aP[4], bP[2];
    const int nch = (K + 31) >> 5;

    auto ldA = [&](int kb) {
        bool full = (kb + 32) <= K;
        #pragma unroll
        for (int i = 0; i < 4; i++) {
            int idx = tid + i * 256;
            int row = idx >> 3, c4 = idx & 7;
            if (full) {
                aP[i] = *(const float4*)(rowp[row] + kb + c4 * 4);
            } else {
                float v[4];
                #pragma unroll
                for (int q = 0; q < 4; q++) {
                    int k = kb + c4 * 4 + q;
                    v[q] = (k < K) ? rowp[row][k] : 0.f;
                }
                aP[i] = make_float4(v[0], v[1], v[2], v[3]);
            }
        }
    };
    auto ldB = [&](int kb) {
        #pragma unroll
        for (int i = 0; i < 2; i++) {
            int idx = tid + i * 256;
            int kr = idx >> 4, c4 = idx & 15;
            int k = kb + kr;
            if (k < K) bP[i] = *(const float4*)(Bmat + (long)k * GG + n0 + c4 * 4);
            else       bP[i] = make_float4(0.f, 0.f, 0.f, 0.f);
        }
    };

    ldA(0); ldB(0);

    for (int c = 0; c < nch; c++) {
        __syncthreads();
        #pragma unroll
        for (int i = 0; i < 4; i++) {
            int idx = tid + i * 256;
            int row = idx >> 3, c4 = idx & 7;
            float4 v = aP[i];
            *(float4*)&As[row * 36 + c4 * 4] =
                make_float4(to_tf32(v.x), to_tf32(v.y), to_tf32(v.z), to_tf32(v.w));
        }
        #pragma unroll
        for (int i = 0; i < 2; i++) {
            int idx = tid + i * 256;
            int kr = idx >> 4, c4 = idx & 15;
            float4 v = bP[i];
            *(float4*)&Bs[kr * 72 + c4 * 4] =
                make_float4(to_tf32(v.x), to_tf32(v.y), to_tf32(v.z), to_tf32(v.w));
        }
        __syncthreads();
        if (c + 1 < nch) { ldA((c + 1) * 32); ldB((c + 1) * 32); }

        #pragma unroll
        for (int kk = 0; kk < 32; kk += 8) {
            uint32_t a[2][4];
            #pragma unroll
            for (int mt = 0; mt < 2; mt++) {
                int rb = mw + mt * 16;
                a[mt][0] = fu(As[(rb + g)     * 36 + kk + t4]);
                a[mt][1] = fu(As[(rb + 8 + g) * 36 + kk + t4]);
                a[mt][2] = fu(As[(rb + g)     * 36 + kk + t4 + 4]);
                a[mt][3] = fu(As[(rb + 8 + g) * 36 + kk + t4 + 4]);
            }
            #pragma unroll
            for (int nt = 0; nt < 4; nt++) {
                uint32_t b0 = fu(Bs[(kk + t4)     * 72 + nw + nt * 8 + g]);
                uint32_t b1 = fu(Bs[(kk + t4 + 4) * 72 + nw + nt * 8 + g]);
                MMA_TF32(acc[0][nt][0], acc[0][nt][1], acc[0][nt][2], acc[0][nt][3],
                         a[0][0], a[0][1], a[0][2], a[0][3], b0, b1);
                MMA_TF32(acc[1][nt][0], acc[1][nt][1], acc[1][nt][2], acc[1][nt][3],
                         a[1][0], a[1][1], a[1][2], a[1][3], b0, b1);
            }
        }
    }

    #pragma unroll
    for (int mt = 0; mt < 2; mt++) {
        #pragma unroll
        for (int nt = 0; nt < 4; nt++) {
            int col = n0 + nw + nt * 8 + 2 * t4;
            float b0 = bias[col], b1 = bias[col + 1];
            long r0 = (long)m0 + mw + mt * 16 + g;
            *(float2*)&g_z[r0 * GG + col] =
                make_float2(acc[mt][nt][0] + b0, acc[mt][nt][1] + b1);
            *(float2*)&g_z[(r0 + 8) * GG + col] =
                make_float2(acc[mt][nt][2] + b0, acc[mt][nt][3] + b1);
        }
    }
}

// ========== persistent LSTM layer: BOTH directions interleaved per block ==========
// 64 blocks, each owns 8 units of BOTH dirs (32 gate cols per dir).
// Per iteration t: step dir0 then dir1; the other dir's compute hides the
// inter-block h-exchange latency of the first.
// SMEM: WsFU [2][32][2][32][4] u32 bf16 frags (both dirs)  64KB
//       As16 [64][520] bf16 shared h buffer               65KB
//       Cs   [64][36]  fp32                                9KB
//       cellc[2][64][8] fp32                               4KB
#define LSTM_SMEM_BYTES (65536 + 66560 + 9216 + 4096)

__global__ __launch_bounds__(256) void lstm_layer(
    const float* __restrict__ recLayer,   // rec + l*U*GG  (dir stride 3*U*GG)
    float* __restrict__ hallOut)
{
    extern __shared__ char smraw[];
    uint32_t*      WsFU  = (uint32_t*)smraw;                         // 2*8192 u32
    __nv_bfloat16* As16  = (__nv_bfloat16*)(smraw + 65536);          // 64*520
    uint32_t*      AsU   = (uint32_t*)As16;                          // stride 260
    float*         Cs    = (float*)(smraw + 65536 + 66560);          // 64*36
    float*         cellc = (float*)(smraw + 65536 + 66560 + 9216);   // 2*64*8

    const int u0 = blockIdx.x * 8;
    const int tid = threadIdx.x;

    // ---- stage weight fragments for BOTH dirs (once per layer) ----
    for (int i = tid; i < 2 * 32 * 4 * 32; i += 256) {
        int dd = i >> 12;
        int r  = i & 4095;
        int cc = r >> 7;
        int nt = (r >> 5) & 3;
        int lane = r & 31;
        int gq = lane >> 2, t4 = lane & 3;
        int col = nt * 8 + gq;                  // 0..31 (nt = gate)
        const float* rec = recLayer + (long)dd * 3 * UU * GG;
        long wcol = (long)(col >> 3) * UU + u0 + (col & 7);
        int k0 = cc * 16 + 2 * t4;
        __nv_bfloat162 b0, b1;
        b0.x = __float2bfloat16_rn(rec[(long)k0 * GG + wcol]);
        b0.y = __float2bfloat16_rn(rec[(long)(k0 + 1) * GG + wcol]);
        b1.x = __float2bfloat16_rn(rec[(long)(k0 + 8) * GG + wcol]);
        b1.y = __float2bfloat16_rn(rec[(long)(k0 + 9) * GG + wcol]);
        uint32_t* dst = WsFU + dd * 8192 +
                        (((cc * 2 + (nt >> 1)) * 32 + lane) << 2) + (nt & 1) * 2;
        dst[0] = *(uint32_t*)&b0;
        dst[1] = *(uint32_t*)&b1;
    }
    for (int i = tid; i < 2 * 64 * 8; i += 256) cellc[i] = 0.f;
    __syncthreads();

    const int w = tid >> 5, lane = tid & 31;
    const int g = lane >> 2, t4 = lane & 3;
    const int mi = w >> 1;        // batch 16-row tile (0..3)
    const int nq = w & 1;         // n-tile pair (0..1) -> 16 of 32 cols

    const int be = tid >> 2;      // epilogue batch row (0..63)
    const int up = tid & 3;       // epilogue unit pair (2 units)

    const int ar0 = (mi * 16 + g) * 260;
    const int ar1 = ar0 + 8 * 260;

    for (int t = 0; t < TT; t++) {
        // ---- prefetch z for both dirs (independent of barriers) ----
        float2 zp[2][4];
        #pragma unroll
        for (int dd = 0; dd < 2; dd++) {
            long base = ((long)dd * TBT + (long)be * TT + t) * GG + u0 + up * 2;
            #pragma unroll
            for (int gate = 0; gate < 4; gate++)
                zp[dd][gate] = *(const float2*)&g_z[base + gate * UU];
        }

        #pragma unroll
        for (int dd = 0; dd < 2; dd++) {
            // ---- wait for h_{t-1}(dd) from all 64 blocks ----
            if (t > 0) {
                if (tid == 0) {
                    const int* p = &g_cnt[dd * TT + (t - 1)];
                    while (acqLd(p) < 64) { }
                }
                __syncthreads();
            }

            // ---- stage A = h_{t-1}(dd) bf16 [64][512] ----
            if (t == 0) {
                uint4 z4 = make_uint4(0, 0, 0, 0);
                for (int i = tid; i < 64 * 64; i += 256) {
                    int row = i >> 6, c8 = i & 63;
                    *(uint4*)(As16 + row * 520 + c8 * 8) = z4;
                }
            } else {
                const int par = (t - 1) & 1;
                const __nv_bfloat16* hb = g_hbf + ((long)(dd * 2 + par) * BB) * UU;
                #pragma unroll
                for (int i = 0; i < 16; i++) {
                    int idx = tid + i * 256;
                    int row = idx >> 6, c8 = idx & 63;
                    uint4 v = *(const uint4*)(hb + row * UU + c8 * 8);
                    *(uint4*)(As16 + row * 520 + c8 * 8) = v;
                }
            }
            __syncthreads();

            // ---- mma: [64x512] @ [512x32], bf16 m16n8k16 ----
            float acc[2][4] = {{0.f,0.f,0.f,0.f},{0.f,0.f,0.f,0.f}};
            const uint32_t* Wd = WsFU + dd * 8192;
            #pragma unroll 4
            for (int cc = 0; cc < 32; cc++) {
                uint32_t a0 = AsU[ar0 + cc * 8 + t4];
                uint32_t a1 = AsU[ar1 + cc * 8 + t4];
                uint32_t a2 = AsU[ar0 + cc * 8 + t4 + 4];
                uint32_t a3 = AsU[ar1 + cc * 8 + t4 + 4];
                uint4 bq = *(const uint4*)&Wd[((cc * 2 + nq) * 32 + lane) << 2];
                MMA_BF16(acc[0][0], acc[0][1], acc[0][2], acc[0][3],
                         a0, a1, a2, a3, bq.x, bq.y);
                MMA_BF16(acc[1][0], acc[1][1], acc[1][2], acc[1][3],
                         a0, a1, a2, a3, bq.z, bq.w);
            }

            // ---- dump fragments to Cs ----
            #pragma unroll
            for (int s = 0; s < 2; s++) {
                int col = (nq * 2 + s) * 8 + 2 * t4;
                int rw = mi * 16 + g;
                *(float2*)&Cs[rw * 36 + col]       = make_float2(acc[s][0], acc[s][1]);
                *(float2*)&Cs[(rw + 8) * 36 + col] = make_float2(acc[s][2], acc[s][3]);
            }
            __syncthreads();

            // ---- gate epilogue: 2 outputs per thread ----
            {
                float2 ci = *(const float2*)&Cs[be * 36 +  0 + up * 2];
                float2 cf = *(const float2*)&Cs[be * 36 +  8 + up * 2];
                float2 cg = *(const float2*)&Cs[be * 36 + 16 + up * 2];
                float2 co = *(const float2*)&Cs[be * 36 + 24 + up * 2];
                float2 cell = *(const float2*)&cellc[dd * 512 + be * 8 + up * 2];
                float2 cn, hn;
                cn.x = sigf(cf.x + zp[dd][1].x) * cell.x
                     + sigf(ci.x + zp[dd][0].x) * ssf(cg.x + zp[dd][2].x);
                cn.y = sigf(cf.y + zp[dd][1].y) * cell.y
                     + sigf(ci.y + zp[dd][0].y) * ssf(cg.y + zp[dd][2].y);
                hn.x = sigf(co.x + zp[dd][3].x) * ssf(cn.x);
                hn.y = sigf(co.y + zp[dd][3].y) * ssf(cn.y);
                *(float2*)&cellc[dd * 512 + be * 8 + up * 2] = cn;
                *(float2*)&hallOut[((long)dd * TBT + (long)be * TT + t) * UU + u0 + up * 2] = hn;
                __nv_bfloat162 pk;
                pk.x = __float2bfloat16_rn(hn.x);
                pk.y = __float2bfloat16_rn(hn.y);
                *(uint32_t*)&g_hbf[((long)(dd * 2 + (t & 1)) * BB + be) * UU + u0 + up * 2] =
                    *(uint32_t*)&pk;
            }

            // ---- all stores done -> release-signal h_t(dd) ----
            __syncthreads();
            if (tid == 0) relAdd(&g_cnt[dd * TT + t]);
        }
    }
}

__global__ void zero_cnt() {
    int i = blockIdx.x * 256 + threadIdx.x;
    if (i < 2 * TT) g_cnt[i] = 0;
}

__global__ void enc_avg() {
    size_t i = (size_t)blockIdx.x * blockDim.x + threadIdx.x;
    if (i < (size_t)TBT * UU)
        g_enc[i] = 0.5f * (g_hall1[i] + g_hall1[(size_t)TBT * UU + i]);
}

// ---------------- attention scores ----------------
__global__ __launch_bounds__(256) void att_scores(
    const float* __restrict__ Wa0, const float* __restrict__ ba0,
    const float* __restrict__ alpha_a, const float* __restrict__ Wa1,
    const float* __restrict__ ba1)
{
    const int b = blockIdx.x;
    const int t0 = blockIdx.y * 16;
    __shared__ float encsT[512][16];
    __shared__ float red[256];
    const int tid = threadIdx.x;

    for (int i = tid; i < 16 * 512; i += 256) {
        int tt = i >> 9, u = i & 511;
        encsT[u][tt] = g_enc[((size_t)b * TT + t0 + tt) * UU + u];
    }
    __syncthreads();

    float a[16];
    float bb = ba0[tid];
    #pragma unroll
    for (int q = 0; q < 16; q++) a[q] = bb;

    for (int u = 0; u < 512; u++) {
        float w = Wa0[u * 256 + tid];
        const float4* row = (const float4*)encsT[u];
        float4 e0 = row[0], e1 = row[1], e2 = row[2], e3 = row[3];
        a[0]  += e0.x * w; a[1]  += e0.y * w; a[2]  += e0.z * w; a[3]  += e0.w * w;
        a[4]  += e1.x * w; a[5]  += e1.y * w; a[6]  += e1.z * w; a[7]  += e1.w * w;
        a[8]  += e2.x * w; a[9]  += e2.y * w; a[10] += e2.z * w; a[11] += e2.w * w;
        a[12] += e3.x * w; a[13] += e3.y * w; a[14] += e3.z * w; a[15] += e3.w * w;
    }

    float al = alpha_a[tid], w1 = Wa1[tid], b1v = ba1[0];
    for (int q = 0; q < 16; q++) {
        float v = a[q];
        v = (v >= 0.f) ? v : al * v;
        v *= w1;
        red[tid] = v; __syncthreads();
        for (int s = 128; s > 0; s >>= 1) {
            if (tid < s) red[tid] += red[tid + s];
            __syncthreads();
        }
        if (tid == 0) g_scores[b * TT + t0 + q] = red[0] + b1v;
        __syncthreads();
    }
}

// ---------------- softmax over T + weighted pooling ----------------
__global__ __launch_bounds__(256) void softmax_pool() {
    const int b = blockIdx.x;
    const int tid = threadIdx.x;
    __shared__ float ws[256];
    __shared__ float red[256];

    float s = g_scores[b * TT + tid];
    red[tid] = s; __syncthreads();
    for (int st = 128; st > 0; st >>= 1) {
        if (tid < st) red[tid] = fmaxf(red[tid], red[tid + st]);
        __syncthreads();
    }
    float mx = red[0]; __syncthreads();
    float e = expf(s - mx);
    red[tid] = e; __syncthreads();
    for (int st = 128; st > 0; st >>= 1) {
        if (tid < st) red[tid] += red[tid + st];
        __syncthreads();
    }
    float sum = red[0]; __syncthreads();
    ws[tid] = e / sum;
    __syncthreads();

    for (int u = tid; u < UU; u += 256) {
        float acc = 0.f;
        for (int t = 0; t < TT; t++)
            acc += g_enc[((size_t)b * TT + t) * UU + u] * ws[t];
        g_pooled[b * UU + u] = acc;
    }
}

// ---------------- classification head ----------------
__global__ __launch_bounds__(256) void head(
    const float* __restrict__ Wd0, const float* __restrict__ bd0,
    const float* __restrict__ gamma, const float* __restrict__ beta,
    const float* __restrict__ bnm, const float* __restrict__ bnv,
    const float* __restrict__ alpha_h, const float* __restrict__ Wd1,
    const float* __restrict__ bd1, float* __restrict__ out)
{
    const int b = blockIdx.x, j = threadIdx.x;
    __shared__ float ps[512];
    __shared__ float hs[256];
    __shared__ float lgs[7];

    for (int u = j; u < 512; u += 256) ps[u] = g_pooled[b * UU + u];
    __syncthreads();

    float h = bd0[j];
    for (int u = 0; u < 512; u++) h += ps[u] * Wd0[u * 256 + j];
    h = (h - bnm[j]) * rsqrtf(bnv[j] + 1e-3f) * gamma[j] + beta[j];
    h = (h >= 0.f) ? h : alpha_h[j] * h;
    hs[j] = h;
    __syncthreads();

    if (j < 7) {
        float lg = bd1[j];
        for (int k = 0; k < 256; k++) lg += hs[k] * Wd1[k * 7 + j];
        lgs[j] = lg;
    }
    __syncthreads();
    if (j == 0) {
        float mx = lgs[0];
        for (int l = 1; l < 7; l++) mx = fmaxf(mx, lgs[l]);
        float sum = 0.f, e[7];
        for (int l = 0; l < 7; l++) { e[l] = expf(lgs[l] - mx); sum += e[l]; }
        for (int l = 0; l < 7; l++) out[b * 7 + l] = e[l] / sum;
    }
}

// ---------------- driver ----------------
extern "C" void kernel_launch(void* const* d_in, const int* in_sizes, int n_in,
                              void* d_out, int out_size)
{
    const int*   ids   = (const int*)  d_in[0];
    const float* emb   = (const float*)d_in[1];
    const float* k0    = (const float*)d_in[2];
    const float* k12   = (const float*)d_in[3];
    const float* rec   = (const float*)d_in[4];
    const float* bias  = (const float*)d_in[5];
    const float* Wa0   = (const float*)d_in[6];
    const float* ba0   = (const float*)d_in[7];
    const float* al_a  = (const float*)d_in[8];
    const float* Wa1   = (const float*)d_in[9];
    const float* ba1   = (const float*)d_in[10];
    const float* Wd0   = (const float*)d_in[11];
    const float* bd0   = (const float*)d_in[12];
    const float* gamma = (const float*)d_in[13];
    const float* beta  = (const float*)d_in[14];
    const float* bnm   = (const float*)d_in[15];
    const float* bnv   = (const float*)d_in[16];
    const float* al_h  = (const float*)d_in[17];
    const float* Wd1   = (const float*)d_in[18];
    const float* bd1   = (const float*)d_in[19];
    float* out = (float*)d_out;

    cudaFuncSetAttribute((const void*)lstm_layer,
                         cudaFuncAttributeMaxDynamicSharedMemorySize, LSTM_SMEM_BYTES);

    dim3 ggrid(M2 / 128, GG / 64);   // (256, 32)

    gemm_mma<<<ggrid, 256>>>(ids, emb, k0, (long)EE * GG, bias, (long)3 * GG, EE, 0);

    for (int l = 0; l < 3; l++) {
        if (l == 1)
            gemm_mma<<<ggrid, 256>>>(ids, emb, k12, (long)2 * UU * GG,
                                     bias + GG, (long)3 * GG, UU, 1);
        if (l == 2)
            gemm_mma<<<ggrid, 256>>>(ids, emb, k12 + (long)UU * GG, (long)2 * UU * GG,
                                     bias + 2 * GG, (long)3 * GG, UU, 2);
        zero_cnt<<<2, 256>>>();
        float* dstp; cudaGetSymbolAddress((void**)&dstp, (l == 1) ? g_hall2 : g_hall1);
        lstm_layer<<<64, 256, LSTM_SMEM_BYTES>>>(rec + (long)l * UU * GG, dstp);
    }

    enc_avg<<<(int)(((size_t)TBT * UU + 255) / 256), 256>>>();
    att_scores<<<dim3(BB, TT / 16), 256>>>(Wa0, ba0, al_a, Wa1, ba1);
    softmax_pool<<<BB, 256>>>();
    head<<<BB, 256>>>(Wd0, bd0, gamma, beta, bnm, bnv, al_h, Wd1, bd1, out);
}

// round 7
// speedup vs baseline: 1.2274x; 1.2274x over previous
#include <cuda_runtime.h>
#include <cuda_bf16.h>
#include <math.h>
#include <stdint.h>

#define BB 64
#define TT 256
#define EE 300
#define UU 512
#define GG 2048
#define TBT (BB*TT)     /* 16384 rows per direction */
#define M2  (2*TBT)     /* 32768 total rows */

// ---------------- device scratch (static allocation only) ----------------
__device__ float g_z[(size_t)M2 * GG];            // [2][B][T][4U]
__device__ float g_hall1[(size_t)2 * TBT * UU];   // [2][B][T][U]
__device__ float g_hall2[(size_t)2 * TBT * UU];   // [2][B][T][U]
__device__ float g_enc[(size_t)TBT * UU];         // [B][T][U]
__device__ float g_scores[TBT];                   // [B][T]
__device__ float g_pooled[BB * UU];               // [B][U]
__device__ int      g_flagH[2 * TT * 32];         // per-dir per-step per-block flags
__device__ uint32_t g_ringA[16 * 4096];           // [d][par][mt][cc][lane][4] bf16 a-frags

__device__ __forceinline__ float sigf(float x) { return 1.f / (1.f + __expf(-x)); }
__device__ __forceinline__ float ssf(float x)  { return x / (1.f + fabsf(x)); }

__device__ __forceinline__ float to_tf32(float x) {
    uint32_t u; asm("cvt.rna.tf32.f32 %0, %1;" : "=r"(u) : "f"(x));
    return __uint_as_float(u);
}
__device__ __forceinline__ uint32_t fu(float x) { return __float_as_uint(x); }

__device__ __forceinline__ void stRel(int* p) {
    asm volatile("st.release.gpu.global.s32 [%0], %1;" :: "l"(p), "r"(1) : "memory");
}
__device__ __forceinline__ int acqLd(const int* p) {
    int v; asm volatile("ld.acquire.gpu.global.s32 %0, [%1];" : "=r"(v) : "l"(p) : "memory");
    return v;
}

#define MMA_TF32(d0,d1,d2,d3,a0,a1,a2,a3,b0,b1) \
    asm volatile("mma.sync.aligned.m16n8k8.row.col.f32.tf32.tf32.f32 " \
        "{%0,%1,%2,%3}, {%4,%5,%6,%7}, {%8,%9}, {%0,%1,%2,%3};" \
        : "+f"(d0), "+f"(d1), "+f"(d2), "+f"(d3) \
        : "r"(a0), "r"(a1), "r"(a2), "r"(a3), "r"(b0), "r"(b1))

#define MMA_BF16(d0,d1,d2,d3,a0,a1,a2,a3,b0,b1) \
    asm volatile("mma.sync.aligned.m16n8k16.row.col.f32.bf16.bf16.f32 " \
        "{%0,%1,%2,%3}, {%4,%5,%6,%7}, {%8,%9}, {%0,%1,%2,%3};" \
        : "+f"(d0), "+f"(d1), "+f"(d2), "+f"(d3) \
        : "r"(a0), "r"(a1), "r"(a2), "r"(a3), "r"(b0), "r"(b1))

// ================= big GEMM via tf32 mma: g_z = A @ Bmat + bias =================
__global__ __launch_bounds__(256) void gemm_mma(
    const int* __restrict__ ids, const float* __restrict__ emb,
    const float* __restrict__ Bbase, long Bstride,
    const float* __restrict__ biasBase, long biasStride,
    int K, int asel)
{
    __shared__ float As[128 * 36];
    __shared__ float Bs[32 * 72];
    __shared__ const float* rowp[128];

    const int m0 = blockIdx.x * 128;
    const int n0 = blockIdx.y * 64;
    const int d  = m0 / TBT;
    const float* Bmat = Bbase + (long)d * Bstride;
    const float* bias = biasBase + (long)d * biasStride;
    const int tid = threadIdx.x;

    if (tid < 128) {
        int m = m0 + tid;
        if (asel == 0) {
            int bt = m % TBT;
            int b = bt / TT, t = bt % TT;
            int tt = d ? (TT - 1 - t) : t;
            rowp[tid] = emb + (long)ids[b * TT + tt] * EE;
        } else {
            const float* hall = (asel == 1) ? g_hall1 : g_hall2;
            rowp[tid] = hall + (long)m * UU;
        }
    }
    __syncthreads();

    const int w = tid >> 5, lane = tid & 31;
    const int g = lane >> 2, t4 = lane & 3;
    const int mw = (w >> 1) * 32;
    const int nw = (w & 1) * 32;

    float acc[2][4][4];
    #pragma unroll
    for (int a = 0; a < 2; a++)
        #pragma unroll
        for (int b = 0; b < 4; b++)
            #pragma unroll
            for (int c = 0; c < 4; c++) acc[a][b][c] = 0.f;

    float4 aP[4], bP[2];
    const int nch = (K + 31) >> 5;

    auto ldA = [&](int kb) {
        bool full = (kb + 32) <= K;
        #pragma unroll
        for (int i = 0; i < 4; i++) {
            int idx = tid + i * 256;
            int row = idx >> 3, c4 = idx & 7;
            if (full) {
                aP[i] = *(const float4*)(rowp[row] + kb + c4 * 4);
            } else {
                float v[4];
                #pragma unroll
                for (int q = 0; q < 4; q++) {
                    int k = kb + c4 * 4 + q;
                    v[q] = (k < K) ? rowp[row][k] : 0.f;
                }
                aP[i] = make_float4(v[0], v[1], v[2], v[3]);
            }
        }
    };
    auto ldB = [&](int kb) {
        #pragma unroll
        for (int i = 0; i < 2; i++) {
            int idx = tid + i * 256;
            int kr = idx >> 4, c4 = idx & 15;
            int k = kb + kr;
            if (k < K) bP[i] = *(const float4*)(Bmat + (long)k * GG + n0 + c4 * 4);
            else       bP[i] = make_float4(0.f, 0.f, 0.f, 0.f);
        }
    };

    ldA(0); ldB(0);

    for (int c = 0; c < nch; c++) {
        __syncthreads();
        #pragma unroll
        for (int i = 0; i < 4; i++) {
            int idx = tid + i * 256;
            int row = idx >> 3, c4 = idx & 7;
            float4 v = aP[i];
            *(float4*)&As[row * 36 + c4 * 4] =
                make_float4(to_tf32(v.x), to_tf32(v.y), to_tf32(v.z), to_tf32(v.w));
        }
        #pragma unroll
        for (int i = 0; i < 2; i++) {
            int idx = tid + i * 256;
            int kr = idx >> 4, c4 = idx & 15;
            float4 v = bP[i];
            *(float4*)&Bs[kr * 72 + c4 * 4] =
                make_float4(to_tf32(v.x), to_tf32(v.y), to_tf32(v.z), to_tf32(v.w));
        }
        __syncthreads();
        if (c + 1 < nch) { ldA((c + 1) * 32); ldB((c + 1) * 32); }

        #pragma unroll
        for (int kk = 0; kk < 32; kk += 8) {
            uint32_t a[2][4];
            #pragma unroll
            for (int mt = 0; mt < 2; mt++) {
                int rb = mw + mt * 16;
                a[mt][0] = fu(As[(rb + g)     * 36 + kk + t4]);
                a[mt][1] = fu(As[(rb + 8 + g) * 36 + kk + t4]);
                a[mt][2] = fu(As[(rb + g)     * 36 + kk + t4 + 4]);
                a[mt][3] = fu(As[(rb + 8 + g) * 36 + kk + t4 + 4]);
            }
            #pragma unroll
            for (int nt = 0; nt < 4; nt++) {
                uint32_t b0 = fu(Bs[(kk + t4)     * 72 + nw + nt * 8 + g]);
                uint32_t b1 = fu(Bs[(kk + t4 + 4) * 72 + nw + nt * 8 + g]);
                MMA_TF32(acc[0][nt][0], acc[0][nt][1], acc[0][nt][2], acc[0][nt][3],
                         a[0][0], a[0][1], a[0][2], a[0][3], b0, b1);
                MMA_TF32(acc[1][nt][0], acc[1][nt][1], acc[1][nt][2], acc[1][nt][3],
                         a[1][0], a[1][1], a[1][2], a[1][3], b0, b1);
            }
        }
    }

    #pragma unroll
    for (int mt = 0; mt < 2; mt++) {
        #pragma unroll
        for (int nt = 0; nt < 4; nt++) {
            int col = n0 + nw + nt * 8 + 2 * t4;
            float b0 = bias[col], b1 = bias[col + 1];
            long r0 = (long)m0 + mw + mt * 16 + g;
            *(float2*)&g_z[r0 * GG + col] =
                make_float2(acc[mt][nt][0] + b0, acc[mt][nt][1] + b1);
            *(float2*)&g_z[(r0 + 8) * GG + col] =
                make_float2(acc[mt][nt][2] + b0, acc[mt][nt][3] + b1);
        }
    }
}

// ================= persistent LSTM layer (R5 topology, frag-ring edition) ========
// 64 blocks: d = bx>>5, slice = bx&31 -> 16 units (64 gate cols).
// A-fragments read DIRECTLY from g_ringA in global (no SMEM staging); the
// epilogue scatters h into fragment layout. Cell state in registers.
// Barrier: 32 per-block release flags polled in parallel by 32 threads.
// SMEM: WsFU 64KB weight frags (resident) + Cs [64][68] fp32.
#define LSTM_SMEM_BYTES (65536 + 64*68*4)

__global__ __launch_bounds__(256) void lstm_layer(
    const float* __restrict__ recLayer,   // rec + l*U*GG  (dir stride 3*U*GG)
    float* __restrict__ hallOut)
{
    extern __shared__ char smraw[];
    uint32_t* WsFU = (uint32_t*)smraw;            // 16384 u32
    float*    Cs   = (float*)(smraw + 65536);     // 64*68

    const int bx = blockIdx.x;
    const int d     = bx >> 5;
    const int slice = bx & 31;
    const int u0    = slice * 16;
    const float* rec = recLayer + (long)d * 3 * UU * GG;
    const int tid = threadIdx.x;

    // ---- stage weight fragments (once per layer) ----
    for (int i = tid; i < 32 * 8 * 32; i += 256) {
        int cc = i >> 8;
        int rem = i & 255;
        int nt = rem >> 5;
        int lane = rem & 31;
        int gq = lane >> 2, t4 = lane & 3;
        int col = nt * 8 + gq;                 // 0..63: gate = col>>4, unit = col&15
        long wcol = (long)(col >> 4) * UU + u0 + (col & 15);
        int k0 = cc * 16 + 2 * t4;
        __nv_bfloat162 b0, b1;
        b0.x = __float2bfloat16_rn(rec[(long)k0 * GG + wcol]);
        b0.y = __float2bfloat16_rn(rec[(long)(k0 + 1) * GG + wcol]);
        b1.x = __float2bfloat16_rn(rec[(long)(k0 + 8) * GG + wcol]);
        b1.y = __float2bfloat16_rn(rec[(long)(k0 + 9) * GG + wcol]);
        uint32_t* dst = WsFU + (((cc * 4 + (nt >> 1)) * 32 + lane) << 2) + (nt & 1) * 2;
        dst[0] = *(uint32_t*)&b0;
        dst[1] = *(uint32_t*)&b1;
    }
    __syncthreads();

    const int w = tid >> 5, lane = tid & 31;
    const int g = lane >> 2, t4 = lane & 3;
    const int mi = w >> 1;        // m-tile (16 batch rows)
    const int nq = w & 1;         // which 4 n-tiles

    const int be = tid & 63;      // epilogue batch row
    const int jq = tid >> 6;      // epilogue unit quad (4 units)

    // epilogue ring-scatter constants
    const int t4a   = (jq & 1) * 2;
    const int reg   = ((be >> 3) & 1) + 2 * (jq >> 1);
    const int mtE   = be >> 4;
    const int laneE = (be & 7) * 4 + t4a;

    float4 cell = make_float4(0.f, 0.f, 0.f, 0.f);

    for (int t = 0; t < TT; t++) {
        // ---- wait for h_{t-1} flags (parallel poll, 32 threads) ----
        if (t > 0) {
            if (tid < 32) {
                const int* p = &g_flagH[(d * TT + (t - 1)) * 32 + tid];
                while (acqLd(p) == 0) { }
            }
            __syncthreads();
        }

        // ---- z loads (likely L2-resident) ----
        long zbase = ((long)d * TBT + (long)be * TT + t) * GG + u0 + jq * 4;
        float4 zi = *(const float4*)&g_z[zbase];
        float4 zf = *(const float4*)&g_z[zbase + UU];
        float4 zg = *(const float4*)&g_z[zbase + 2 * UU];
        float4 zo = *(const float4*)&g_z[zbase + 3 * UU];

        // ---- mma: [64x512] @ [512x64], A-frags streamed from global ring ----
        float acc[4][4];
        #pragma unroll
        for (int q = 0; q < 4; q++)
            #pragma unroll
            for (int r = 0; r < 4; r++) acc[q][r] = 0.f;

        if (t > 0) {
            const int par = (t - 1) & 1;
            const uint4* ring =
                (const uint4*)&g_ringA[(((d * 2 + par) * 4) + mi) * 4096];
            uint4 abuf[8];
            #pragma unroll
            for (int i = 0; i < 8; i++) abuf[i] = ring[i * 32 + lane];
            #pragma unroll
            for (int cc = 0; cc < 32; cc++) {
                uint4 av = abuf[cc & 7];
                if (cc + 8 < 32) abuf[cc & 7] = ring[(cc + 8) * 32 + lane];
                uint4 bq0 = *(const uint4*)&WsFU[((cc * 4 + nq * 2)     * 32 + lane) << 2];
                uint4 bq1 = *(const uint4*)&WsFU[((cc * 4 + nq * 2 + 1) * 32 + lane) << 2];
                MMA_BF16(acc[0][0], acc[0][1], acc[0][2], acc[0][3],
                         av.x, av.y, av.z, av.w, bq0.x, bq0.y);
                MMA_BF16(acc[1][0], acc[1][1], acc[1][2], acc[1][3],
                         av.x, av.y, av.z, av.w, bq0.z, bq0.w);
                MMA_BF16(acc[2][0], acc[2][1], acc[2][2], acc[2][3],
                         av.x, av.y, av.z, av.w, bq1.x, bq1.y);
                MMA_BF16(acc[3][0], acc[3][1], acc[3][2], acc[3][3],
                         av.x, av.y, av.z, av.w, bq1.z, bq1.w);
            }
        }

        // ---- dump fragments to Cs ----
        #pragma unroll
        for (int q = 0; q < 4; q++) {
            int col = (nq * 4 + q) * 8 + 2 * t4;
            int rw = mi * 16 + g;
            *(float2*)&Cs[rw * 68 + col]       = make_float2(acc[q][0], acc[q][1]);
            *(float2*)&Cs[(rw + 8) * 68 + col] = make_float2(acc[q][2], acc[q][3]);
        }
        __syncthreads();

        // ---- gate epilogue: 4 outputs per thread (batch be, units jq*4..+3) ----
        {
            float4 ci = *(const float4*)&Cs[be * 68 +  0 + jq * 4];
            float4 cf = *(const float4*)&Cs[be * 68 + 16 + jq * 4];
            float4 cg = *(const float4*)&Cs[be * 68 + 32 + jq * 4];
            float4 co = *(const float4*)&Cs[be * 68 + 48 + jq * 4];
            float4 cn, hn;
            cn.x = sigf(cf.x + zf.x) * cell.x + sigf(ci.x + zi.x) * ssf(cg.x + zg.x);
            cn.y = sigf(cf.y + zf.y) * cell.y + sigf(ci.y + zi.y) * ssf(cg.y + zg.y);
            cn.z = sigf(cf.z + zf.z) * cell.z + sigf(ci.z + zi.z) * ssf(cg.z + zg.z);
            cn.w = sigf(cf.w + zf.w) * cell.w + sigf(ci.w + zi.w) * ssf(cg.w + zg.w);
            hn.x = sigf(co.x + zo.x) * ssf(cn.x);
            hn.y = sigf(co.y + zo.y) * ssf(cn.y);
            hn.z = sigf(co.z + zo.z) * ssf(cn.z);
            hn.w = sigf(co.w + zo.w) * ssf(cn.w);
            cell = cn;
            *(float4*)&hallOut[((long)d * TBT + (long)be * TT + t) * UU + u0 + jq * 4] = hn;

            // scatter h into A-fragment ring layout (bf16)
            __nv_bfloat162 p0, p1;
            p0.x = __float2bfloat16_rn(hn.x); p0.y = __float2bfloat16_rn(hn.y);
            p1.x = __float2bfloat16_rn(hn.z); p1.y = __float2bfloat16_rn(hn.w);
            uint32_t* rw = &g_ringA[(((d * 2 + (t & 1)) * 4) + mtE) * 4096
                                    + (slice * 32 + laneE) * 4 + reg];
            rw[0] = *(uint32_t*)&p0;
            rw[4] = *(uint32_t*)&p1;     // lane+1, same reg
        }

        // ---- all stores done -> release flag for this block's slice ----
        __syncthreads();
        if (tid == 0) stRel(&g_flagH[(d * TT + t) * 32 + slice]);
    }
}

__global__ void zero_flags() {
    int i = blockIdx.x * 256 + threadIdx.x;
    if (i < 2 * TT * 32) g_flagH[i] = 0;
}

__global__ void enc_avg() {
    size_t i = (size_t)blockIdx.x * blockDim.x + threadIdx.x;
    if (i < (size_t)TBT * UU)
        g_enc[i] = 0.5f * (g_hall1[i] + g_hall1[(size_t)TBT * UU + i]);
}

// ---------------- attention scores ----------------
__global__ __launch_bounds__(256) void att_scores(
    const float* __restrict__ Wa0, const float* __restrict__ ba0,
    const float* __restrict__ alpha_a, const float* __restrict__ Wa1,
    const float* __restrict__ ba1)
{
    const int b = blockIdx.x;
    const int t0 = blockIdx.y * 16;
    __shared__ float encsT[512][16];
    __shared__ float red[256];
    const int tid = threadIdx.x;

    for (int i = tid; i < 16 * 512; i += 256) {
        int tt = i >> 9, u = i & 511;
        encsT[u][tt] = g_enc[((size_t)b * TT + t0 + tt) * UU + u];
    }
    __syncthreads();

    float a[16];
    float bb = ba0[tid];
    #pragma unroll
    for (int q = 0; q < 16; q++) a[q] = bb;

    for (int u = 0; u < 512; u++) {
        float w = Wa0[u * 256 + tid];
        const float4* row = (const float4*)encsT[u];
        float4 e0 = row[0], e1 = row[1], e2 = row[2], e3 = row[3];
        a[0]  += e0.x * w; a[1]  += e0.y * w; a[2]  += e0.z * w; a[3]  += e0.w * w;
        a[4]  += e1.x * w; a[5]  += e1.y * w; a[6]  += e1.z * w; a[7]  += e1.w * w;
        a[8]  += e2.x * w; a[9]  += e2.y * w; a[10] += e2.z * w; a[11] += e2.w * w;
        a[12] += e3.x * w; a[13] += e3.y * w; a[14] += e3.z * w; a[15] += e3.w * w;
    }

    float al = alpha_a[tid], w1 = Wa1[tid], b1v = ba1[0];
    for (int q = 0; q < 16; q++) {
        float v = a[q];
        v = (v >= 0.f) ? v : al * v;
        v *= w1;
        red[tid] = v; __syncthreads();
        for (int s = 128; s > 0; s >>= 1) {
            if (tid < s) red[tid] += red[tid + s];
            __syncthreads();
        }
        if (tid == 0) g_scores[b * TT + t0 + q] = red[0] + b1v;
        __syncthreads();
    }
}

// ---------------- softmax over T + weighted pooling ----------------
__global__ __launch_bounds__(256) void softmax_pool() {
    const int b = blockIdx.x;
    const int tid = threadIdx.x;
    __shared__ float ws[256];
    __shared__ float red[256];

    float s = g_scores[b * TT + tid];
    red[tid] = s; __syncthreads();
    for (int st = 128; st > 0; st >>= 1) {
        if (tid < st) red[tid] = fmaxf(red[tid], red[tid + st]);
        __syncthreads();
    }
    float mx = red[0]; __syncthreads();
    float e = expf(s - mx);
    red[tid] = e; __syncthreads();
    for (int st = 128; st > 0; st >>= 1) {
        if (tid < st) red[tid] += red[tid + st];
        __syncthreads();
    }
    float sum = red[0]; __syncthreads();
    ws[tid] = e / sum;
    __syncthreads();

    for (int u = tid; u < UU; u += 256) {
        float acc = 0.f;
        for (int t = 0; t < TT; t++)
            acc += g_enc[((size_t)b * TT + t) * UU + u] * ws[t];
        g_pooled[b * UU + u] = acc;
    }
}

// ---------------- classification head ----------------
__global__ __launch_bounds__(256) void head(
    const float* __restrict__ Wd0, const float* __restrict__ bd0,
    const float* __restrict__ gamma, const float* __restrict__ beta,
    const float* __restrict__ bnm, const float* __restrict__ bnv,
    const float* __restrict__ alpha_h, const float* __restrict__ Wd1,
    const float* __restrict__ bd1, float* __restrict__ out)
{
    const int b = blockIdx.x, j = threadIdx.x;
    __shared__ float ps[512];
    __shared__ float hs[256];
    __shared__ float lgs[7];

    for (int u = j; u < 512; u += 256) ps[u] = g_pooled[b * UU + u];
    __syncthreads();

    float h = bd0[j];
    for (int u = 0; u < 512; u++) h += ps[u] * Wd0[u * 256 + j];
    h = (h - bnm[j]) * rsqrtf(bnv[j] + 1e-3f) * gamma[j] + beta[j];
    h = (h >= 0.f) ? h : alpha_h[j] * h;
    hs[j] = h;
    __syncthreads();

    if (j < 7) {
        float lg = bd1[j];
        for (int k = 0; k < 256; k++) lg += hs[k] * Wd1[k * 7 + j];
        lgs[j] = lg;
    }
    __syncthreads();
    if (j == 0) {
        float mx = lgs[0];
        for (int l = 1; l < 7; l++) mx = fmaxf(mx, lgs[l]);
        float sum = 0.f, e[7];
        for (int l = 0; l < 7; l++) { e[l] = expf(lgs[l] - mx); sum += e[l]; }
        for (int l = 0; l < 7; l++) out[b * 7 + l] = e[l] / sum;
    }
}

// ---------------- driver ----------------
extern "C" void kernel_launch(void* const* d_in, const int* in_sizes, int n_in,
                              void* d_out, int out_size)
{
    const int*   ids   = (const int*)  d_in[0];
    const float* emb   = (const float*)d_in[1];
    const float* k0    = (const float*)d_in[2];
    const float* k12   = (const float*)d_in[3];
    const float* rec   = (const float*)d_in[4];
    const float* bias  = (const float*)d_in[5];
    const float* Wa0   = (const float*)d_in[6];
    const float* ba0   = (const float*)d_in[7];
    const float* al_a  = (const float*)d_in[8];
    const float* Wa1   = (const float*)d_in[9];
    const float* ba1   = (const float*)d_in[10];
    const float* Wd0   = (const float*)d_in[11];
    const float* bd0   = (const float*)d_in[12];
    const float* gamma = (const float*)d_in[13];
    const float* beta  = (const float*)d_in[14];
    const float* bnm   = (const float*)d_in[15];
    const float* bnv   = (const float*)d_in[16];
    const float* al_h  = (const float*)d_in[17];
    const float* Wd1   = (const float*)d_in[18];
    const float* bd1   = (const float*)d_in[19];
    float* out = (float*)d_out;

    cudaFuncSetAttribute((const void*)lstm_layer,
                         cudaFuncAttributeMaxDynamicSharedMemorySize, LSTM_SMEM_BYTES);

    dim3 ggrid(M2 / 128, GG / 64);   // (256, 32)

    gemm_mma<<<ggrid, 256>>>(ids, emb, k0, (long)EE * GG, bias, (long)3 * GG, EE, 0);

    for (int l = 0; l < 3; l++) {
        if (l == 1)
            gemm_mma<<<ggrid, 256>>>(ids, emb, k12, (long)2 * UU * GG,
                                     bias + GG, (long)3 * GG, UU, 1);
        if (l == 2)
            gemm_mma<<<ggrid, 256>>>(ids, emb, k12 + (long)UU * GG, (long)2 * UU * GG,
                                     bias + 2 * GG, (long)3 * GG, UU, 2);
        zero_flags<<<64, 256>>>();
        float* dstp; cudaGetSymbolAddress((void**)&dstp, (l == 1) ? g_hall2 : g_hall1);
        lstm_layer<<<64, 256, LSTM_SMEM_BYTES>>>(rec + (long)l * UU * GG, dstp);
    }

    enc_avg<<<(int)(((size_t)TBT * UU + 255) / 256), 256>>>();
    att_scores<<<dim3(BB, TT / 16), 256>>>(Wa0, ba0, al_a, Wa1, ba1);
    softmax_pool<<<BB, 256>>>();
    head<<<BB, 256>>>(Wd0, bd0, gamma, beta, bnm, bnv, al_h, Wd1, bd1, out);
}

// round 8
// speedup vs baseline: 1.4965x; 1.2193x over previous
#include <cuda_runtime.h>
#include <cuda_bf16.h>
#include <math.h>
#include <stdint.h>

#define BB 64
#define TT 256
#define EE 300
#define UU 512
#define GG 2048
#define TBT (BB*TT)     /* 16384 rows per direction */
#define M2  (2*TBT)     /* 32768 total rows */

// ---------------- device scratch (static allocation only) ----------------
__device__ float g_z[(size_t)M2 * GG];            // [2][B][T][4U] (layer-0 input proj)
__device__ float g_hall1[(size_t)2 * TBT * UU];   // [2][B][T][U]  final-layer h (fp32)
__device__ float g_enc[(size_t)TBT * UU];         // [B][T][U]
__device__ float g_scores[TBT];                   // [B][T]
__device__ float g_pooled[BB * UU];               // [B][U]
__device__ int g_flagH[2 * TT * 32];              // layer-0 per-step per-block flags
__device__ int g_flagW[2 * 2 * TT * 32];          // [stage][dir][t][slice] wave flags
// full-T bf16 A-fragment rings: [dir][t][mt][4096] u32
__device__ uint32_t g_ring1[(size_t)2 * TT * 4 * 4096];   // h1 (layer0 out)
__device__ uint32_t g_ring2[(size_t)2 * TT * 4 * 4096];   // h2 (layer1 out)
__device__ uint32_t g_ring3[(size_t)2 * TT * 4 * 4096];   // h3 (layer2 out)

__device__ __forceinline__ float sigf(float x) { return 1.f / (1.f + __expf(-x)); }
__device__ __forceinline__ float ssf(float x)  { return x / (1.f + fabsf(x)); }

__device__ __forceinline__ float to_tf32(float x) {
    uint32_t u; asm("cvt.rna.tf32.f32 %0, %1;" : "=r"(u) : "f"(x));
    return __uint_as_float(u);
}
__device__ __forceinline__ uint32_t fu(float x) { return __float_as_uint(x); }

__device__ __forceinline__ void stRel(int* p) {
    asm volatile("st.release.gpu.global.s32 [%0], %1;" :: "l"(p), "r"(1) : "memory");
}
__device__ __forceinline__ int acqLd(const int* p) {
    int v; asm volatile("ld.acquire.gpu.global.s32 %0, [%1];" : "=r"(v) : "l"(p) : "memory");
    return v;
}

#define MMA_TF32(d0,d1,d2,d3,a0,a1,a2,a3,b0,b1) \
    asm volatile("mma.sync.aligned.m16n8k8.row.col.f32.tf32.tf32.f32 " \
        "{%0,%1,%2,%3}, {%4,%5,%6,%7}, {%8,%9}, {%0,%1,%2,%3};" \
        : "+f"(d0), "+f"(d1), "+f"(d2), "+f"(d3) \
        : "r"(a0), "r"(a1), "r"(a2), "r"(a3), "r"(b0), "r"(b1))

#define MMA_BF16(d0,d1,d2,d3,a0,a1,a2,a3,b0,b1) \
    asm volatile("mma.sync.aligned.m16n8k16.row.col.f32.bf16.bf16.f32 " \
        "{%0,%1,%2,%3}, {%4,%5,%6,%7}, {%8,%9}, {%0,%1,%2,%3};" \
        : "+f"(d0), "+f"(d1), "+f"(d2), "+f"(d3) \
        : "r"(a0), "r"(a1), "r"(a2), "r"(a3), "r"(b0), "r"(b1))

// ================= big GEMM (layer-0 input proj only): g_z = emb[ids] @ k0 + bias ====
__global__ __launch_bounds__(256) void gemm_mma(
    const int* __restrict__ ids, const float* __restrict__ emb,
    const float* __restrict__ Bbase, long Bstride,
    const float* __restrict__ biasBase, long biasStride, int K)
{
    __shared__ float As[128 * 36];
    __shared__ float Bs[32 * 72];
    __shared__ const float* rowp[128];

    const int m0 = blockIdx.x * 128;
    const int n0 = blockIdx.y * 64;
    const int d  = m0 / TBT;
    const float* Bmat = Bbase + (long)d * Bstride;
    const float* bias = biasBase + (long)d * biasStride;
    const int tid = threadIdx.x;

    if (tid < 128) {
        int m = m0 + tid;
        int bt = m % TBT;
        int b = bt / TT, t = bt % TT;
        int tt = d ? (TT - 1 - t) : t;
        rowp[tid] = emb + (long)ids[b * TT + tt] * EE;
    }
    __syncthreads();

    const int w = tid >> 5, lane = tid & 31;
    const int g = lane >> 2, t4 = lane & 3;
    const int mw = (w >> 1) * 32;
    const int nw = (w & 1) * 32;

    float acc[2][4][4];
    #pragma unroll
    for (int a = 0; a < 2; a++)
        #pragma unroll
        for (int b = 0; b < 4; b++)
            #pragma unroll
            for (int c = 0; c < 4; c++) acc[a][b][c] = 0.f;

    float4 aP[4], bP[2];
    const int nch = (K + 31) >> 5;

    auto ldA = [&](int kb) {
        bool full = (kb + 32) <= K;
        #pragma unroll
        for (int i = 0; i < 4; i++) {
            int idx = tid + i * 256;
            int row = idx >> 3, c4 = idx & 7;
            if (full) {
                aP[i] = *(const float4*)(rowp[row] + kb + c4 * 4);
            } else {
                float v[4];
                #pragma unroll
                for (int q = 0; q < 4; q++) {
                    int k = kb + c4 * 4 + q;
                    v[q] = (k < K) ? rowp[row][k] : 0.f;
                }
                aP[i] = make_float4(v[0], v[1], v[2], v[3]);
            }
        }
    };
    auto ldB = [&](int kb) {
        #pragma unroll
        for (int i = 0; i < 2; i++) {
            int idx = tid + i * 256;
            int kr = idx >> 4, c4 = idx & 15;
            int k = kb + kr;
            if (k < K) bP[i] = *(const float4*)(Bmat + (long)k * GG + n0 + c4 * 4);
            else       bP[i] = make_float4(0.f, 0.f, 0.f, 0.f);
        }
    };

    ldA(0); ldB(0);

    for (int c = 0; c < nch; c++) {
        __syncthreads();
        #pragma unroll
        for (int i = 0; i < 4; i++) {
            int idx = tid + i * 256;
            int row = idx >> 3, c4 = idx & 7;
            float4 v = aP[i];
            *(float4*)&As[row * 36 + c4 * 4] =
                make_float4(to_tf32(v.x), to_tf32(v.y), to_tf32(v.z), to_tf32(v.w));
        }
        #pragma unroll
        for (int i = 0; i < 2; i++) {
            int idx = tid + i * 256;
            int kr = idx >> 4, c4 = idx & 15;
            float4 v = bP[i];
            *(float4*)&Bs[kr * 72 + c4 * 4] =
                make_float4(to_tf32(v.x), to_tf32(v.y), to_tf32(v.z), to_tf32(v.w));
        }
        __syncthreads();
        if (c + 1 < nch) { ldA((c + 1) * 32); ldB((c + 1) * 32); }

        #pragma unroll
        for (int kk = 0; kk < 32; kk += 8) {
            uint32_t a[2][4];
            #pragma unroll
            for (int mt = 0; mt < 2; mt++) {
                int rb = mw + mt * 16;
                a[mt][0] = fu(As[(rb + g)     * 36 + kk + t4]);
                a[mt][1] = fu(As[(rb + 8 + g) * 36 + kk + t4]);
                a[mt][2] = fu(As[(rb + g)     * 36 + kk + t4 + 4]);
                a[mt][3] = fu(As[(rb + 8 + g) * 36 + kk + t4 + 4]);
            }
            #pragma unroll
            for (int nt = 0; nt < 4; nt++) {
                uint32_t b0 = fu(Bs[(kk + t4)     * 72 + nw + nt * 8 + g]);
                uint32_t b1 = fu(Bs[(kk + t4 + 4) * 72 + nw + nt * 8 + g]);
                MMA_TF32(acc[0][nt][0], acc[0][nt][1], acc[0][nt][2], acc[0][nt][3],
                         a[0][0], a[0][1], a[0][2], a[0][3], b0, b1);
                MMA_TF32(acc[1][nt][0], acc[1][nt][1], acc[1][nt][2], acc[1][nt][3],
                         a[1][0], a[1][1], a[1][2], a[1][3], b0, b1);
            }
        }
    }

    #pragma unroll
    for (int mt = 0; mt < 2; mt++) {
        #pragma unroll
        for (int nt = 0; nt < 4; nt++) {
            int col = n0 + nw + nt * 8 + 2 * t4;
            float b0 = bias[col], b1 = bias[col + 1];
            long r0 = (long)m0 + mw + mt * 16 + g;
            *(float2*)&g_z[r0 * GG + col] =
                make_float2(acc[mt][nt][0] + b0, acc[mt][nt][1] + b1);
            *(float2*)&g_z[(r0 + 8) * GG + col] =
                make_float2(acc[mt][nt][2] + b0, acc[mt][nt][3] + b1);
        }
    }
}

// ---- shared helper: stage a 512x64-gate-col weight slice as bf16 mma fragments ----
__device__ __forceinline__ void stage_wfrags(
    uint32_t* dstW, const float* W, int u0, int tid)
{
    for (int i = tid; i < 32 * 8 * 32; i += 256) {
        int cc = i >> 8;
        int rem = i & 255;
        int nt = rem >> 5;
        int lane = rem & 31;
        int gq = lane >> 2, t4 = lane & 3;
        int col = nt * 8 + gq;                 // gate = col>>4, unit = col&15
        long wcol = (long)(col >> 4) * UU + u0 + (col & 15);
        int k0 = cc * 16 + 2 * t4;
        __nv_bfloat162 b0, b1;
        b0.x = __float2bfloat16_rn(W[(long)k0 * GG + wcol]);
        b0.y = __float2bfloat16_rn(W[(long)(k0 + 1) * GG + wcol]);
        b1.x = __float2bfloat16_rn(W[(long)(k0 + 8) * GG + wcol]);
        b1.y = __float2bfloat16_rn(W[(long)(k0 + 9) * GG + wcol]);
        uint32_t* dst = dstW + (((cc * 4 + (nt >> 1)) * 32 + lane) << 2) + (nt & 1) * 2;
        dst[0] = *(uint32_t*)&b0;
        dst[1] = *(uint32_t*)&b1;
    }
}

// ================= layer-0 persistent recurrence (R7 kernel, full-T ring) =========
#define L0_SMEM_BYTES (65536 + 64*68*4)

__global__ __launch_bounds__(256) void lstm0(const float* __restrict__ recBase)
{
    extern __shared__ char smraw[];
    uint32_t* WsFU = (uint32_t*)smraw;            // 16384 u32
    float*    Cs   = (float*)(smraw + 65536);     // 64*68

    const int bx = blockIdx.x;
    const int d     = bx >> 5;
    const int slice = bx & 31;
    const int u0    = slice * 16;
    const int tid = threadIdx.x;

    stage_wfrags(WsFU, recBase + (long)d * 3 * UU * GG, u0, tid);
    __syncthreads();

    const int w = tid >> 5, lane = tid & 31;
    const int g = lane >> 2, t4 = lane & 3;
    const int mi = w >> 1;
    const int nq = w & 1;

    const int be = tid & 63;
    const int jq = tid >> 6;

    const int t4a   = (jq & 1) * 2;
    const int reg   = ((be >> 3) & 1) + 2 * (jq >> 1);
    const int mtE   = be >> 4;
    const int laneE = (be & 7) * 4 + t4a;

    float4 cell = make_float4(0.f, 0.f, 0.f, 0.f);

    for (int t = 0; t < TT; t++) {
        if (t > 0) {
            if (tid < 32) {
                const int* p = &g_flagH[(d * TT + (t - 1)) * 32 + tid];
                while (acqLd(p) == 0) { }
            }
            __syncthreads();
        }

        long zbase = ((long)d * TBT + (long)be * TT + t) * GG + u0 + jq * 4;
        float4 zi = *(const float4*)&g_z[zbase];
        float4 zf = *(const float4*)&g_z[zbase + UU];
        float4 zg = *(const float4*)&g_z[zbase + 2 * UU];
        float4 zo = *(const float4*)&g_z[zbase + 3 * UU];

        float acc[4][4];
        #pragma unroll
        for (int q = 0; q < 4; q++)
            #pragma unroll
            for (int r = 0; r < 4; r++) acc[q][r] = 0.f;

        if (t > 0) {
            const uint4* ring =
                (const uint4*)&g_ring1[(((size_t)(d * TT + (t - 1))) * 4 + mi) * 4096];
            uint4 abuf[8];
            #pragma unroll
            for (int i = 0; i < 8; i++) abuf[i] = ring[i * 32 + lane];
            #pragma unroll
            for (int cc = 0; cc < 32; cc++) {
                uint4 av = abuf[cc & 7];
                if (cc + 8 < 32) abuf[cc & 7] = ring[(cc + 8) * 32 + lane];
                uint4 bq0 = *(const uint4*)&WsFU[((cc * 4 + nq * 2)     * 32 + lane) << 2];
                uint4 bq1 = *(const uint4*)&WsFU[((cc * 4 + nq * 2 + 1) * 32 + lane) << 2];
                MMA_BF16(acc[0][0], acc[0][1], acc[0][2], acc[0][3],
                         av.x, av.y, av.z, av.w, bq0.x, bq0.y);
                MMA_BF16(acc[1][0], acc[1][1], acc[1][2], acc[1][3],
                         av.x, av.y, av.z, av.w, bq0.z, bq0.w);
                MMA_BF16(acc[2][0], acc[2][1], acc[2][2], acc[2][3],
                         av.x, av.y, av.z, av.w, bq1.x, bq1.y);
                MMA_BF16(acc[3][0], acc[3][1], acc[3][2], acc[3][3],
                         av.x, av.y, av.z, av.w, bq1.z, bq1.w);
            }
        }

        #pragma unroll
        for (int q = 0; q < 4; q++) {
            int col = (nq * 4 + q) * 8 + 2 * t4;
            int rw = mi * 16 + g;
            *(float2*)&Cs[rw * 68 + col]       = make_float2(acc[q][0], acc[q][1]);
            *(float2*)&Cs[(rw + 8) * 68 + col] = make_float2(acc[q][2], acc[q][3]);
        }
        __syncthreads();

        {
            float4 ci = *(const float4*)&Cs[be * 68 +  0 + jq * 4];
            float4 cf = *(const float4*)&Cs[be * 68 + 16 + jq * 4];
            float4 cg = *(const float4*)&Cs[be * 68 + 32 + jq * 4];
            float4 co = *(const float4*)&Cs[be * 68 + 48 + jq * 4];
            float4 cn, hn;
            cn.x = sigf(cf.x + zf.x) * cell.x + sigf(ci.x + zi.x) * ssf(cg.x + zg.x);
            cn.y = sigf(cf.y + zf.y) * cell.y + sigf(ci.y + zi.y) * ssf(cg.y + zg.y);
            cn.z = sigf(cf.z + zf.z) * cell.z + sigf(ci.z + zi.z) * ssf(cg.z + zg.z);
            cn.w = sigf(cf.w + zf.w) * cell.w + sigf(ci.w + zi.w) * ssf(cg.w + zg.w);
            hn.x = sigf(co.x + zo.x) * ssf(cn.x);
            hn.y = sigf(co.y + zo.y) * ssf(cn.y);
            hn.z = sigf(co.z + zo.z) * ssf(cn.z);
            hn.w = sigf(co.w + zo.w) * ssf(cn.w);
            cell = cn;
            __nv_bfloat162 p0, p1;
            p0.x = __float2bfloat16_rn(hn.x); p0.y = __float2bfloat16_rn(hn.y);
            p1.x = __float2bfloat16_rn(hn.z); p1.y = __float2bfloat16_rn(hn.w);
            uint32_t* rw = &g_ring1[(((size_t)(d * TT + t)) * 4 + mtE) * 4096
                                    + (slice * 32 + laneE) * 4 + reg];
            rw[0] = *(uint32_t*)&p0;
            rw[4] = *(uint32_t*)&p1;
        }

        __syncthreads();
        if (tid == 0) stRel(&g_flagH[(d * TT + t) * 32 + slice]);
    }
}

// ============== wavefront layers 1+2: k12-projection mma fused in-step ============
// 128 blocks: stage = bx>>6 (0: layer1, 1: layer2), d = (bx>>5)&1, slice = bx&31.
// Stage s at time t: acc = h_in[t] @ k12  +  h_own[t-1] @ rec;  gates; bias in epilogue.
// h_in: ring1 (s=0, fully ready) or ring2 (s=1, flag-gated per t).
#define WAVE_SMEM_BYTES (131072 + 64*68*4)

__global__ __launch_bounds__(256) void wave12(
    const float* __restrict__ recBase, const float* __restrict__ k12Base,
    const float* __restrict__ biasBase)
{
    extern __shared__ char smraw[];
    uint32_t* WsK = (uint32_t*)smraw;              // k12 frags  16384 u32
    uint32_t* WsR = WsK + 16384;                   // rec frags  16384 u32
    float*    Cs  = (float*)(smraw + 131072);      // 64*68

    const int bx = blockIdx.x;
    const int stage = bx >> 6;
    const int d     = (bx >> 5) & 1;
    const int slice = bx & 31;
    const int u0    = slice * 16;
    const int tid = threadIdx.x;

    stage_wfrags(WsK, k12Base + ((long)d * 2 + stage) * UU * GG, u0, tid);
    stage_wfrags(WsR, recBase + ((long)d * 3 + stage + 1) * UU * GG, u0, tid);
    __syncthreads();

    const uint32_t* ringIn = stage ? g_ring2 : g_ring1;
    uint32_t*       ringOut = stage ? g_ring3 : g_ring2;
    int* flagsOwn = &g_flagW[(stage * 2 + d) * TT * 32];
    const int* flagsIn = &g_flagW[(0 * 2 + d) * TT * 32];   // stage0 flags (h2)

    const int w = tid >> 5, lane = tid & 31;
    const int g = lane >> 2, t4 = lane & 3;
    const int mi = w >> 1;
    const int nq = w & 1;

    const int be = tid & 63;
    const int jq = tid >> 6;

    const int t4a   = (jq & 1) * 2;
    const int reg   = ((be >> 3) & 1) + 2 * (jq >> 1);
    const int mtE   = be >> 4;
    const int laneE = (be & 7) * 4 + t4a;

    // bias (layer stage+1, dir d) into registers
    const float* biasL = biasBase + ((long)d * 3 + stage + 1) * GG;
    float4 bi = *(const float4*)&biasL[0 * UU + u0 + jq * 4];
    float4 bf4 = *(const float4*)&biasL[1 * UU + u0 + jq * 4];
    float4 bg4 = *(const float4*)&biasL[2 * UU + u0 + jq * 4];
    float4 bo4 = *(const float4*)&biasL[3 * UU + u0 + jq * 4];

    float4 cell = make_float4(0.f, 0.f, 0.f, 0.f);

    for (int t = 0; t < TT; t++) {
        // ---- waits: own h[t-1] flags; stage1 also input h2[t] flags ----
        {
            bool need = false;
            const int* p = 0;
            if (tid < 32 && t > 0) { p = &flagsOwn[(t - 1) * 32 + tid]; need = true; }
            else if (tid >= 32 && tid < 64 && stage == 1) {
                p = &flagsIn[t * 32 + (tid - 32)]; need = true;
            }
            if (need) { while (acqLd(p) == 0) { } }
            if (t > 0 || stage == 1) __syncthreads();
        }

        float acc[4][4];
        #pragma unroll
        for (int q = 0; q < 4; q++)
            #pragma unroll
            for (int r = 0; r < 4; r++) acc[q][r] = 0.f;

        const uint4* rin =
            (const uint4*)&ringIn[(((size_t)(d * TT + t)) * 4 + mi) * 4096];

        if (t == 0) {
            // input-projection stream only
            uint4 abuf[4];
            #pragma unroll
            for (int i = 0; i < 4; i++) abuf[i] = rin[i * 32 + lane];
            #pragma unroll
            for (int cc = 0; cc < 32; cc++) {
                uint4 av = abuf[cc & 3];
                if (cc + 4 < 32) abuf[cc & 3] = rin[(cc + 4) * 32 + lane];
                uint4 bq0 = *(const uint4*)&WsK[((cc * 4 + nq * 2)     * 32 + lane) << 2];
                uint4 bq1 = *(const uint4*)&WsK[((cc * 4 + nq * 2 + 1) * 32 + lane) << 2];
                MMA_BF16(acc[0][0], acc[0][1], acc[0][2], acc[0][3],
                         av.x, av.y, av.z, av.w, bq0.x, bq0.y);
                MMA_BF16(acc[1][0], acc[1][1], acc[1][2], acc[1][3],
                         av.x, av.y, av.z, av.w, bq0.z, bq0.w);
                MMA_BF16(acc[2][0], acc[2][1], acc[2][2], acc[2][3],
                         av.x, av.y, av.z, av.w, bq1.x, bq1.y);
                MMA_BF16(acc[3][0], acc[3][1], acc[3][2], acc[3][3],
                         av.x, av.y, av.z, av.w, bq1.z, bq1.w);
            }
        } else {
            const uint4* rrec =
                (const uint4*)&ringOut[(((size_t)(d * TT + (t - 1))) * 4 + mi) * 4096];
            uint4 bufI[4], bufR[4];
            #pragma unroll
            for (int i = 0; i < 4; i++) { bufI[i] = rin[i * 32 + lane];
                                          bufR[i] = rrec[i * 32 + lane]; }
            #pragma unroll
            for (int cc = 0; cc < 32; cc++) {
                uint4 ai = bufI[cc & 3];
                uint4 ar = bufR[cc & 3];
                if (cc + 4 < 32) { bufI[cc & 3] = rin[(cc + 4) * 32 + lane];
                                   bufR[cc & 3] = rrec[(cc + 4) * 32 + lane]; }
                uint4 bk0 = *(const uint4*)&WsK[((cc * 4 + nq * 2)     * 32 + lane) << 2];
                uint4 bk1 = *(const uint4*)&WsK[((cc * 4 + nq * 2 + 1) * 32 + lane) << 2];
                uint4 br0 = *(const uint4*)&WsR[((cc * 4 + nq * 2)     * 32 + lane) << 2];
                uint4 br1 = *(const uint4*)&WsR[((cc * 4 + nq * 2 + 1) * 32 + lane) << 2];
                MMA_BF16(acc[0][0], acc[0][1], acc[0][2], acc[0][3],
                         ai.x, ai.y, ai.z, ai.w, bk0.x, bk0.y);
                MMA_BF16(acc[1][0], acc[1][1], acc[1][2], acc[1][3],
                         ai.x, ai.y, ai.z, ai.w, bk0.z, bk0.w);
                MMA_BF16(acc[2][0], acc[2][1], acc[2][2], acc[2][3],
                         ai.x, ai.y, ai.z, ai.w, bk1.x, bk1.y);
                MMA_BF16(acc[3][0], acc[3][1], acc[3][2], acc[3][3],
                         ai.x, ai.y, ai.z, ai.w, bk1.z, bk1.w);
                MMA_BF16(acc[0][0], acc[0][1], acc[0][2], acc[0][3],
                         ar.x, ar.y, ar.z, ar.w, br0.x, br0.y);
                MMA_BF16(acc[1][0], acc[1][1], acc[1][2], acc[1][3],
                         ar.x, ar.y, ar.z, ar.w, br0.z, br0.w);
                MMA_BF16(acc[2][0], acc[2][1], acc[2][2], acc[2][3],
                         ar.x, ar.y, ar.z, ar.w, br1.x, br1.y);
                MMA_BF16(acc[3][0], acc[3][1], acc[3][2], acc[3][3],
                         ar.x, ar.y, ar.z, ar.w, br1.z, br1.w);
            }
        }

        #pragma unroll
        for (int q = 0; q < 4; q++) {
            int col = (nq * 4 + q) * 8 + 2 * t4;
            int rw = mi * 16 + g;
            *(float2*)&Cs[rw * 68 + col]       = make_float2(acc[q][0], acc[q][1]);
            *(float2*)&Cs[(rw + 8) * 68 + col] = make_float2(acc[q][2], acc[q][3]);
        }
        __syncthreads();

        {
            float4 ci = *(const float4*)&Cs[be * 68 +  0 + jq * 4];
            float4 cf = *(const float4*)&Cs[be * 68 + 16 + jq * 4];
            float4 cg = *(const float4*)&Cs[be * 68 + 32 + jq * 4];
            float4 co = *(const float4*)&Cs[be * 68 + 48 + jq * 4];
            float4 cn, hn;
            cn.x = sigf(cf.x + bf4.x) * cell.x + sigf(ci.x + bi.x) * ssf(cg.x + bg4.x);
            cn.y = sigf(cf.y + bf4.y) * cell.y + sigf(ci.y + bi.y) * ssf(cg.y + bg4.y);
            cn.z = sigf(cf.z + bf4.z) * cell.z + sigf(ci.z + bi.z) * ssf(cg.z + bg4.z);
            cn.w = sigf(cf.w + bf4.w) * cell.w + sigf(ci.w + bi.w) * ssf(cg.w + bg4.w);
            hn.x = sigf(co.x + bo4.x) * ssf(cn.x);
            hn.y = sigf(co.y + bo4.y) * ssf(cn.y);
            hn.z = sigf(co.z + bo4.z) * ssf(cn.z);
            hn.w = sigf(co.w + bo4.w) * ssf(cn.w);
            cell = cn;
            if (stage == 1)
                *(float4*)&g_hall1[((long)d * TBT + (long)be * TT + t) * UU + u0 + jq * 4] = hn;
            __nv_bfloat162 p0, p1;
            p0.x = __float2bfloat16_rn(hn.x); p0.y = __float2bfloat16_rn(hn.y);
            p1.x = __float2bfloat16_rn(hn.z); p1.y = __float2bfloat16_rn(hn.w);
            uint32_t* rw = &ringOut[(((size_t)(d * TT + t)) * 4 + mtE) * 4096
                                    + (slice * 32 + laneE) * 4 + reg];
            rw[0] = *(uint32_t*)&p0;
            rw[4] = *(uint32_t*)&p1;
        }

        __syncthreads();
        if (tid == 0) stRel(&flagsOwn[t * 32 + slice]);
    }
}

__global__ void zero_flags() {
    int i = blockIdx.x * 256 + threadIdx.x;
    if (i < 2 * TT * 32) g_flagH[i] = 0;
    if (i < 2 * 2 * TT * 32) g_flagW[i] = 0;
}

__global__ void enc_avg() {
    size_t i = (size_t)blockIdx.x * blockDim.x + threadIdx.x;
    if (i < (size_t)TBT * UU)
        g_enc[i] = 0.5f * (g_hall1[i] + g_hall1[(size_t)TBT * UU + i]);
}

// ---------------- attention scores ----------------
__global__ __launch_bounds__(256) void att_scores(
    const float* __restrict__ Wa0, const float* __restrict__ ba0,
    const float* __restrict__ alpha_a, const float* __restrict__ Wa1,
    const float* __restrict__ ba1)
{
    const int b = blockIdx.x;
    const int t0 = blockIdx.y * 16;
    __shared__ float encsT[512][16];
    __shared__ float red[256];
    const int tid = threadIdx.x;

    for (int i = tid; i < 16 * 512; i += 256) {
        int tt = i >> 9, u = i & 511;
        encsT[u][tt] = g_enc[((size_t)b * TT + t0 + tt) * UU + u];
    }
    __syncthreads();

    float a[16];
    float bb = ba0[tid];
    #pragma unroll
    for (int q = 0; q < 16; q++) a[q] = bb;

    for (int u = 0; u < 512; u++) {
        float w = Wa0[u * 256 + tid];
        const float4* row = (const float4*)encsT[u];
        float4 e0 = row[0], e1 = row[1], e2 = row[2], e3 = row[3];
        a[0]  += e0.x * w; a[1]  += e0.y * w; a[2]  += e0.z * w; a[3]  += e0.w * w;
        a[4]  += e1.x * w; a[5]  += e1.y * w; a[6]  += e1.z * w; a[7]  += e1.w * w;
        a[8]  += e2.x * w; a[9]  += e2.y * w; a[10] += e2.z * w; a[11] += e2.w * w;
        a[12] += e3.x * w; a[13] += e3.y * w; a[14] += e3.z * w; a[15] += e3.w * w;
    }

    float al = alpha_a[tid], w1 = Wa1[tid], b1v = ba1[0];
    for (int q = 0; q < 16; q++) {
        float v = a[q];
        v = (v >= 0.f) ? v : al * v;
        v *= w1;
        red[tid] = v; __syncthreads();
        for (int s = 128; s > 0; s >>= 1) {
            if (tid < s) red[tid] += red[tid + s];
            __syncthreads();
        }
        if (tid == 0) g_scores[b * TT + t0 + q] = red[0] + b1v;
        __syncthreads();
    }
}

// ---------------- softmax over T + weighted pooling ----------------
__global__ __launch_bounds__(256) void softmax_pool() {
    const int b = blockIdx.x;
    const int tid = threadIdx.x;
    __shared__ float ws[256];
    __shared__ float red[256];

    float s = g_scores[b * TT + tid];
    red[tid] = s; __syncthreads();
    for (int st = 128; st > 0; st >>= 1) {
        if (tid < st) red[tid] = fmaxf(red[tid], red[tid + st]);
        __syncthreads();
    }
    float mx = red[0]; __syncthreads();
    float e = expf(s - mx);
    red[tid] = e; __syncthreads();
    for (int st = 128; st > 0; st >>= 1) {
        if (tid < st) red[tid] += red[tid + st];
        __syncthreads();
    }
    float sum = red[0]; __syncthreads();
    ws[tid] = e / sum;
    __syncthreads();

    for (int u = tid; u < UU; u += 256) {
        float acc = 0.f;
        for (int t = 0; t < TT; t++)
            acc += g_enc[((size_t)b * TT + t) * UU + u] * ws[t];
        g_pooled[b * UU + u] = acc;
    }
}

// ---------------- classification head ----------------
__global__ __launch_bounds__(256) void head(
    const float* __restrict__ Wd0, const float* __restrict__ bd0,
    const float* __restrict__ gamma, const float* __restrict__ beta,
    const float* __restrict__ bnm, const float* __restrict__ bnv,
    const float* __restrict__ alpha_h, const float* __restrict__ Wd1,
    const float* __restrict__ bd1, float* __restrict__ out)
{
    const int b = blockIdx.x, j = threadIdx.x;
    __shared__ float ps[512];
    __shared__ float hs[256];
    __shared__ float lgs[7];

    for (int u = j; u < 512; u += 256) ps[u] = g_pooled[b * UU + u];
    __syncthreads();

    float h = bd0[j];
    for (int u = 0; u < 512; u++) h += ps[u] * Wd0[u * 256 + j];
    h = (h - bnm[j]) * rsqrtf(bnv[j] + 1e-3f) * gamma[j] + beta[j];
    h = (h >= 0.f) ? h : alpha_h[j] * h;
    hs[j] = h;
    __syncthreads();

    if (j < 7) {
        float lg = bd1[j];
        for (int k = 0; k < 256; k++) lg += hs[k] * Wd1[k * 7 + j];
        lgs[j] = lg;
    }
    __syncthreads();
    if (j == 0) {
        float mx = lgs[0];
        for (int l = 1; l < 7; l++) mx = fmaxf(mx, lgs[l]);
        float sum = 0.f, e[7];
        for (int l = 0; l < 7; l++) { e[l] = expf(lgs[l] - mx); sum += e[l]; }
        for (int l = 0; l < 7; l++) out[b * 7 + l] = e[l] / sum;
    }
}

// ---------------- driver ----------------
extern "C" void kernel_launch(void* const* d_in, const int* in_sizes, int n_in,
                              void* d_out, int out_size)
{
    const int*   ids   = (const int*)  d_in[0];
    const float* emb   = (const float*)d_in[1];
    const float* k0    = (const float*)d_in[2];
    const float* k12   = (const float*)d_in[3];
    const float* rec   = (const float*)d_in[4];
    const float* bias  = (const float*)d_in[5];
    const float* Wa0   = (const float*)d_in[6];
    const float* ba0   = (const float*)d_in[7];
    const float* al_a  = (const float*)d_in[8];
    const float* Wa1   = (const float*)d_in[9];
    const float* ba1   = (const float*)d_in[10];
    const float* Wd0   = (const float*)d_in[11];
    const float* bd0   = (const float*)d_in[12];
    const float* gamma = (const float*)d_in[13];
    const float* beta  = (const float*)d_in[14];
    const float* bnm   = (const float*)d_in[15];
    const float* bnv   = (const float*)d_in[16];
    const float* al_h  = (const float*)d_in[17];
    const float* Wd1   = (const float*)d_in[18];
    const float* bd1   = (const float*)d_in[19];
    float* out = (float*)d_out;

    cudaFuncSetAttribute((const void*)lstm0,
                         cudaFuncAttributeMaxDynamicSharedMemorySize, L0_SMEM_BYTES);
    cudaFuncSetAttribute((const void*)wave12,
                         cudaFuncAttributeMaxDynamicSharedMemorySize, WAVE_SMEM_BYTES);

    dim3 ggrid(M2 / 128, GG / 64);   // (256, 32)

    // layer-0 input projection (embedding gather fused), both directions
    gemm_mma<<<ggrid, 256>>>(ids, emb, k0, (long)EE * GG, bias, (long)3 * GG, EE);
    zero_flags<<<128, 256>>>();
    lstm0<<<64, 256, L0_SMEM_BYTES>>>(rec);
    wave12<<<128, 256, WAVE_SMEM_BYTES>>>(rec, k12, bias);

    enc_avg<<<(int)(((size_t)TBT * UU + 255) / 256), 256>>>();
    att_scores<<<dim3(BB, TT / 16), 256>>>(Wa0, ba0, al_a, Wa1, ba1);
    softmax_pool<<<BB, 256>>>();
    head<<<BB, 256>>>(Wd0, bd0, gamma, beta, bnm, bnv, al_h, Wd1, bd1, out);
}

// round 9
// speedup vs baseline: 1.9649x; 1.3130x over previous
#include <cuda_runtime.h>
#include <cuda_bf16.h>
#include <math.h>
#include <stdint.h>

#define BB 64
#define TT 256
#define EE 300
#define UU 512
#define GG 2048
#define TBT (BB*TT)     /* 16384 rows per direction */
#define M2  (2*TBT)     /* 32768 total rows */

// ---------------- device scratch (static allocation only) ----------------
__device__ float g_z[(size_t)M2 * GG];            // [2][B][T][4U] (layer-0 input proj)
__device__ float g_hall1[(size_t)2 * TBT * UU];   // [2][B][T][U]  final-layer h (fp32)
__device__ float g_enc[(size_t)TBT * UU];         // [B][T][U]
__device__ float g_scores[TBT];                   // [B][T]
__device__ float g_pooled[BB * UU];               // [B][U]
__device__ int g_flagF[(TT + 2) * 128];           // [iter][dir*64+slice]
// full-T bf16 A-fragment rings: [dir][t][mt][4096] u32
__device__ uint32_t g_ring1[(size_t)2 * TT * 4 * 4096];   // h1 (layer0 out)
__device__ uint32_t g_ring2[(size_t)2 * TT * 4 * 4096];   // h2 (layer1 out)
__device__ uint32_t g_ring3[(size_t)2 * TT * 4 * 4096];   // h3 (layer2 out)

__device__ __forceinline__ float sigf(float x) { return 1.f / (1.f + __expf(-x)); }
__device__ __forceinline__ float ssf(float x)  { return x / (1.f + fabsf(x)); }

__device__ __forceinline__ float to_tf32(float x) {
    uint32_t u; asm("cvt.rna.tf32.f32 %0, %1;" : "=r"(u) : "f"(x));
    return __uint_as_float(u);
}
__device__ __forceinline__ uint32_t fu(float x) { return __float_as_uint(x); }

__device__ __forceinline__ void stRel(int* p) {
    asm volatile("st.release.gpu.global.s32 [%0], %1;" :: "l"(p), "r"(1) : "memory");
}
__device__ __forceinline__ int acqLd(const int* p) {
    int v; asm volatile("ld.acquire.gpu.global.s32 %0, [%1];" : "=r"(v) : "l"(p) : "memory");
    return v;
}

#define MMA_TF32(d0,d1,d2,d3,a0,a1,a2,a3,b0,b1) \
    asm volatile("mma.sync.aligned.m16n8k8.row.col.f32.tf32.tf32.f32 " \
        "{%0,%1,%2,%3}, {%4,%5,%6,%7}, {%8,%9}, {%0,%1,%2,%3};" \
        : "+f"(d0), "+f"(d1), "+f"(d2), "+f"(d3) \
        : "r"(a0), "r"(a1), "r"(a2), "r"(a3), "r"(b0), "r"(b1))

#define MMA_BF16(d0,d1,d2,d3,a0,a1,a2,a3,b0,b1) \
    asm volatile("mma.sync.aligned.m16n8k16.row.col.f32.bf16.bf16.f32 " \
        "{%0,%1,%2,%3}, {%4,%5,%6,%7}, {%8,%9}, {%0,%1,%2,%3};" \
        : "+f"(d0), "+f"(d1), "+f"(d2), "+f"(d3) \
        : "r"(a0), "r"(a1), "r"(a2), "r"(a3), "r"(b0), "r"(b1))

// ================= big GEMM (layer-0 input proj): g_z = emb[ids] @ k0 + bias ====
__global__ __launch_bounds__(256) void gemm_mma(
    const int* __restrict__ ids, const float* __restrict__ emb,
    const float* __restrict__ Bbase, long Bstride,
    const float* __restrict__ biasBase, long biasStride, int K)
{
    __shared__ float As[128 * 36];
    __shared__ float Bs[32 * 72];
    __shared__ const float* rowp[128];

    const int m0 = blockIdx.x * 128;
    const int n0 = blockIdx.y * 64;
    const int d  = m0 / TBT;
    const float* Bmat = Bbase + (long)d * Bstride;
    const float* bias = biasBase + (long)d * biasStride;
    const int tid = threadIdx.x;

    if (tid < 128) {
        int m = m0 + tid;
        int bt = m % TBT;
        int b = bt / TT, t = bt % TT;
        int tt = d ? (TT - 1 - t) : t;
        rowp[tid] = emb + (long)ids[b * TT + tt] * EE;
    }
    __syncthreads();

    const int w = tid >> 5, lane = tid & 31;
    const int g = lane >> 2, t4 = lane & 3;
    const int mw = (w >> 1) * 32;
    const int nw = (w & 1) * 32;

    float acc[2][4][4];
    #pragma unroll
    for (int a = 0; a < 2; a++)
        #pragma unroll
        for (int b = 0; b < 4; b++)
            #pragma unroll
            for (int c = 0; c < 4; c++) acc[a][b][c] = 0.f;

    float4 aP[4], bP[2];
    const int nch = (K + 31) >> 5;

    auto ldA = [&](int kb) {
        bool full = (kb + 32) <= K;
        #pragma unroll
        for (int i = 0; i < 4; i++) {
            int idx = tid + i * 256;
            int row = idx >> 3, c4 = idx & 7;
            if (full) {
                aP[i] = *(const float4*)(rowp[row] + kb + c4 * 4);
            } else {
                float v[4];
                #pragma unroll
                for (int q = 0; q < 4; q++) {
                    int k = kb + c4 * 4 + q;
                    v[q] = (k < K) ? rowp[row][k] : 0.f;
                }
                aP[i] = make_float4(v[0], v[1], v[2], v[3]);
            }
        }
    };
    auto ldB = [&](int kb) {
        #pragma unroll
        for (int i = 0; i < 2; i++) {
            int idx = tid + i * 256;
            int kr = idx >> 4, c4 = idx & 15;
            int k = kb + kr;
            if (k < K) bP[i] = *(const float4*)(Bmat + (long)k * GG + n0 + c4 * 4);
            else       bP[i] = make_float4(0.f, 0.f, 0.f, 0.f);
        }
    };

    ldA(0); ldB(0);

    for (int c = 0; c < nch; c++) {
        __syncthreads();
        #pragma unroll
        for (int i = 0; i < 4; i++) {
            int idx = tid + i * 256;
            int row = idx >> 3, c4 = idx & 7;
            float4 v = aP[i];
            *(float4*)&As[row * 36 + c4 * 4] =
                make_float4(to_tf32(v.x), to_tf32(v.y), to_tf32(v.z), to_tf32(v.w));
        }
        #pragma unroll
        for (int i = 0; i < 2; i++) {
            int idx = tid + i * 256;
            int kr = idx >> 4, c4 = idx & 15;
            float4 v = bP[i];
            *(float4*)&Bs[kr * 72 + c4 * 4] =
                make_float4(to_tf32(v.x), to_tf32(v.y), to_tf32(v.z), to_tf32(v.w));
        }
        __syncthreads();
        if (c + 1 < nch) { ldA((c + 1) * 32); ldB((c + 1) * 32); }

        #pragma unroll
        for (int kk = 0; kk < 32; kk += 8) {
            uint32_t a[2][4];
            #pragma unroll
            for (int mt = 0; mt < 2; mt++) {
                int rb = mw + mt * 16;
                a[mt][0] = fu(As[(rb + g)     * 36 + kk + t4]);
                a[mt][1] = fu(As[(rb + 8 + g) * 36 + kk + t4]);
                a[mt][2] = fu(As[(rb + g)     * 36 + kk + t4 + 4]);
                a[mt][3] = fu(As[(rb + 8 + g) * 36 + kk + t4 + 4]);
            }
            #pragma unroll
            for (int nt = 0; nt < 4; nt++) {
                uint32_t b0 = fu(Bs[(kk + t4)     * 72 + nw + nt * 8 + g]);
                uint32_t b1 = fu(Bs[(kk + t4 + 4) * 72 + nw + nt * 8 + g]);
                MMA_TF32(acc[0][nt][0], acc[0][nt][1], acc[0][nt][2], acc[0][nt][3],
                         a[0][0], a[0][1], a[0][2], a[0][3], b0, b1);
                MMA_TF32(acc[1][nt][0], acc[1][nt][1], acc[1][nt][2], acc[1][nt][3],
                         a[1][0], a[1][1], a[1][2], a[1][3], b0, b1);
            }
        }
    }

    #pragma unroll
    for (int mt = 0; mt < 2; mt++) {
        #pragma unroll
        for (int nt = 0; nt < 4; nt++) {
            int col = n0 + nw + nt * 8 + 2 * t4;
            float b0 = bias[col], b1 = bias[col + 1];
            long r0 = (long)m0 + mw + mt * 16 + g;
            *(float2*)&g_z[r0 * GG + col] =
                make_float2(acc[mt][nt][0] + b0, acc[mt][nt][1] + b1);
            *(float2*)&g_z[(r0 + 8) * GG + col] =
                make_float2(acc[mt][nt][2] + b0, acc[mt][nt][3] + b1);
        }
    }
}

// ---- stage a 512x32-gate-col weight slice as bf16 B-fragments (R6-validated) ----
__device__ __forceinline__ void stage_wfrags32(
    uint32_t* dstW, const float* W, int u0, int tid)
{
    for (int i = tid; i < 32 * 4 * 32; i += 256) {
        int cc = i >> 7;
        int nt = (i >> 5) & 3;
        int lane = i & 31;
        int gq = lane >> 2, t4 = lane & 3;
        int col = nt * 8 + gq;                 // gate = col>>3, unit = col&7
        long wcol = (long)(col >> 3) * UU + u0 + (col & 7);
        int k0 = cc * 16 + 2 * t4;
        __nv_bfloat162 b0, b1;
        b0.x = __float2bfloat16_rn(W[(long)k0 * GG + wcol]);
        b0.y = __float2bfloat16_rn(W[(long)(k0 + 1) * GG + wcol]);
        b1.x = __float2bfloat16_rn(W[(long)(k0 + 8) * GG + wcol]);
        b1.y = __float2bfloat16_rn(W[(long)(k0 + 9) * GG + wcol]);
        uint32_t* dst = dstW + (((cc * 2 + (nt >> 1)) * 32 + lane) << 2) + (nt & 1) * 2;
        dst[0] = *(uint32_t*)&b0;
        dst[1] = *(uint32_t*)&b1;
    }
}

// ---- one bf16 mma stream: acc += A(ring frags) @ B(Ws frags), C = 16x16/warp ----
__device__ __forceinline__ void mma_stream(
    float acc[2][4], const uint32_t* ring, const uint32_t* Ws, int lane, int nq)
{
    const uint4* r = (const uint4*)ring;
    uint4 buf[4];
    #pragma unroll
    for (int i = 0; i < 4; i++) buf[i] = r[i * 32 + lane];
    #pragma unroll
    for (int cc = 0; cc < 32; cc++) {
        uint4 av = buf[cc & 3];
        if (cc + 4 < 32) buf[cc & 3] = r[(cc + 4) * 32 + lane];
        uint4 bq = *(const uint4*)&Ws[((cc * 2 + nq) * 32 + lane) << 2];
        MMA_BF16(acc[0][0], acc[0][1], acc[0][2], acc[0][3],
                 av.x, av.y, av.z, av.w, bq.x, bq.y);
        MMA_BF16(acc[1][0], acc[1][1], acc[1][2], acc[1][3],
                 av.x, av.y, av.z, av.w, bq.z, bq.w);
    }
}

// ============ fully-fused 3-layer bidirectional LSTM wavefront ============
// 128 blocks: d = bx>>6, slice = bx&63 -> 8 units (32 gate cols) for ALL 3 layers.
// Iteration i: stage0@t=i, stage1@t=i-1, stage2@t=i-2. All deps from iter i-1
// -> ONE flag wave per iteration. TT+2 iterations total.
#define FUSED_SMEM_BYTES (163840 + 3*64*36*4)

__global__ __launch_bounds__(256) void fused_lstm(
    const float* __restrict__ recBase, const float* __restrict__ k12Base,
    const float* __restrict__ biasBase)
{
    extern __shared__ char smraw[];
    uint32_t* Ws0  = (uint32_t*)smraw;         // rec layer0
    uint32_t* Ws1k = Ws0 + 8192;               // k12 layer1
    uint32_t* Ws1r = Ws0 + 16384;              // rec layer1
    uint32_t* Ws2k = Ws0 + 24576;              // k12 layer2
    uint32_t* Ws2r = Ws0 + 32768;              // rec layer2
    float*    Cs   = (float*)(smraw + 163840); // [3][64][36]

    const int bx = blockIdx.x;
    const int d     = bx >> 6;
    const int slice = bx & 63;
    const int u0    = slice * 8;
    const int tid = threadIdx.x;

    stage_wfrags32(Ws0,  recBase + ((long)d * 3 + 0) * UU * GG, u0, tid);
    stage_wfrags32(Ws1k, k12Base + ((long)d * 2 + 0) * UU * GG, u0, tid);
    stage_wfrags32(Ws1r, recBase + ((long)d * 3 + 1) * UU * GG, u0, tid);
    stage_wfrags32(Ws2k, k12Base + ((long)d * 2 + 1) * UU * GG, u0, tid);
    stage_wfrags32(Ws2r, recBase + ((long)d * 3 + 2) * UU * GG, u0, tid);
    __syncthreads();

    const int lane = tid & 31;
    const int mi = (tid >> 5) >> 1;   // m-tile
    const int nq = (tid >> 5) & 1;    // col half

    const int be = tid >> 2;          // epilogue batch row (0..63)
    const int up = tid & 3;           // unit pair -> units u0+up*2, +1

    // ring scatter constants (slice-parity fold; see derivation in analysis)
    const int sIdx = ((slice >> 1) * 32 + (be & 7) * 4 + up) * 4
                     + ((be >> 3) & 1) + 2 * (slice & 1);
    const int mtE = be >> 4;

    // biases for layers 1,2 (layer0 bias already folded into g_z)
    const float* b1p = biasBase + ((long)d * 3 + 1) * GG;
    const float* b2p = biasBase + ((long)d * 3 + 2) * GG;
    float2 b1g[4], b2g[4];
    #pragma unroll
    for (int gate = 0; gate < 4; gate++) {
        b1g[gate] = *(const float2*)&b1p[gate * UU + u0 + up * 2];
        b2g[gate] = *(const float2*)&b2p[gate * UU + u0 + up * 2];
    }

    float2 cell0 = make_float2(0.f, 0.f);
    float2 cell1 = make_float2(0.f, 0.f);
    float2 cell2 = make_float2(0.f, 0.f);

    for (int i = 0; i < TT + 2; i++) {
        const bool s0 = (i < TT);
        const bool s1 = (i >= 1 && i <= TT);
        const bool s2 = (i >= 2);
        const int t0 = i, t1 = i - 1, t2 = i - 2;

        // ---- prefetch z for stage0 (flag-independent) ----
        float2 z0[4];
        if (s0) {
            long zb = ((long)d * TBT + (long)be * TT + t0) * GG + u0 + up * 2;
            #pragma unroll
            for (int gate = 0; gate < 4; gate++)
                z0[gate] = *(const float2*)&g_z[zb + gate * UU];
        }

        // ---- single wait: all same-dir blocks' iteration i-1 flags ----
        if (i > 0) {
            if (tid < 64) {
                const int* p = &g_flagF[(i - 1) * 128 + d * 64 + tid];
                while (acqLd(p) == 0) { }
            }
            __syncthreads();
        }

        // ---- mma for all active stages (registers only) ----
        float a0[2][4] = {{0,0,0,0},{0,0,0,0}};
        float a1[2][4] = {{0,0,0,0},{0,0,0,0}};
        float a2[2][4] = {{0,0,0,0},{0,0,0,0}};

        if (s0 && t0 > 0)
            mma_stream(a0, &g_ring1[((size_t)(d * TT + t0 - 1) * 4 + mi) * 4096],
                       Ws0, lane, nq);
        if (s1) {
            mma_stream(a1, &g_ring1[((size_t)(d * TT + t1) * 4 + mi) * 4096],
                       Ws1k, lane, nq);
            if (t1 > 0)
                mma_stream(a1, &g_ring2[((size_t)(d * TT + t1 - 1) * 4 + mi) * 4096],
                           Ws1r, lane, nq);
        }
        if (s2) {
            mma_stream(a2, &g_ring2[((size_t)(d * TT + t2) * 4 + mi) * 4096],
                       Ws2k, lane, nq);
            if (t2 > 0)
                mma_stream(a2, &g_ring3[((size_t)(d * TT + t2 - 1) * 4 + mi) * 4096],
                           Ws2r, lane, nq);
        }
        __syncthreads();   // protect previous iteration's Cs reads

        // ---- dump fragments ----
        {
            const int t4 = lane & 3, g = lane >> 2;
            const int rw = mi * 16 + g;
            #pragma unroll
            for (int s = 0; s < 2; s++) {
                int col = (nq * 2 + s) * 8 + 2 * t4;
                if (s0) {
                    *(float2*)&Cs[0 * 2304 + rw * 36 + col]       = make_float2(a0[s][0], a0[s][1]);
                    *(float2*)&Cs[0 * 2304 + (rw + 8) * 36 + col] = make_float2(a0[s][2], a0[s][3]);
                }
                if (s1) {
                    *(float2*)&Cs[1 * 2304 + rw * 36 + col]       = make_float2(a1[s][0], a1[s][1]);
                    *(float2*)&Cs[1 * 2304 + (rw + 8) * 36 + col] = make_float2(a1[s][2], a1[s][3]);
                }
                if (s2) {
                    *(float2*)&Cs[2 * 2304 + rw * 36 + col]       = make_float2(a2[s][0], a2[s][1]);
                    *(float2*)&Cs[2 * 2304 + (rw + 8) * 36 + col] = make_float2(a2[s][2], a2[s][3]);
                }
            }
        }
        __syncthreads();

        // ---- epilogues ----
        if (s0) {
            float2 ci = *(const float2*)&Cs[0 * 2304 + be * 36 +  0 + up * 2];
            float2 cf = *(const float2*)&Cs[0 * 2304 + be * 36 +  8 + up * 2];
            float2 cg = *(const float2*)&Cs[0 * 2304 + be * 36 + 16 + up * 2];
            float2 co = *(const float2*)&Cs[0 * 2304 + be * 36 + 24 + up * 2];
            float2 cn, hn;
            cn.x = sigf(cf.x + z0[1].x) * cell0.x + sigf(ci.x + z0[0].x) * ssf(cg.x + z0[2].x);
            cn.y = sigf(cf.y + z0[1].y) * cell0.y + sigf(ci.y + z0[0].y) * ssf(cg.y + z0[2].y);
            hn.x = sigf(co.x + z0[3].x) * ssf(cn.x);
            hn.y = sigf(co.y + z0[3].y) * ssf(cn.y);
            cell0 = cn;
            __nv_bfloat162 pk;
            pk.x = __float2bfloat16_rn(hn.x); pk.y = __float2bfloat16_rn(hn.y);
            g_ring1[((size_t)(d * TT + t0) * 4 + mtE) * 4096 + sIdx] = *(uint32_t*)&pk;
        }
        if (s1) {
            float2 ci = *(const float2*)&Cs[1 * 2304 + be * 36 +  0 + up * 2];
            float2 cf = *(const float2*)&Cs[1 * 2304 + be * 36 +  8 + up * 2];
            float2 cg = *(const float2*)&Cs[1 * 2304 + be * 36 + 16 + up * 2];
            float2 co = *(const float2*)&Cs[1 * 2304 + be * 36 + 24 + up * 2];
            float2 cn, hn;
            cn.x = sigf(cf.x + b1g[1].x) * cell1.x + sigf(ci.x + b1g[0].x) * ssf(cg.x + b1g[2].x);
            cn.y = sigf(cf.y + b1g[1].y) * cell1.y + sigf(ci.y + b1g[0].y) * ssf(cg.y + b1g[2].y);
            hn.x = sigf(co.x + b1g[3].x) * ssf(cn.x);
            hn.y = sigf(co.y + b1g[3].y) * ssf(cn.y);
            cell1 = cn;
            __nv_bfloat162 pk;
            pk.x = __float2bfloat16_rn(hn.x); pk.y = __float2bfloat16_rn(hn.y);
            g_ring2[((size_t)(d * TT + t1) * 4 + mtE) * 4096 + sIdx] = *(uint32_t*)&pk;
        }
        if (s2) {
            float2 ci = *(const float2*)&Cs[2 * 2304 + be * 36 +  0 + up * 2];
            float2 cf = *(const float2*)&Cs[2 * 2304 + be * 36 +  8 + up * 2];
            float2 cg = *(const float2*)&Cs[2 * 2304 + be * 36 + 16 + up * 2];
            float2 co = *(const float2*)&Cs[2 * 2304 + be * 36 + 24 + up * 2];
            float2 cn, hn;
            cn.x = sigf(cf.x + b2g[1].x) * cell2.x + sigf(ci.x + b2g[0].x) * ssf(cg.x + b2g[2].x);
            cn.y = sigf(cf.y + b2g[1].y) * cell2.y + sigf(ci.y + b2g[0].y) * ssf(cg.y + b2g[2].y);
            hn.x = sigf(co.x + b2g[3].x) * ssf(cn.x);
            hn.y = sigf(co.y + b2g[3].y) * ssf(cn.y);
            cell2 = cn;
            *(float2*)&g_hall1[((long)d * TBT + (long)be * TT + t2) * UU + u0 + up * 2] = hn;
            __nv_bfloat162 pk;
            pk.x = __float2bfloat16_rn(hn.x); pk.y = __float2bfloat16_rn(hn.y);
            g_ring3[((size_t)(d * TT + t2) * 4 + mtE) * 4096 + sIdx] = *(uint32_t*)&pk;
        }

        // ---- signal this block's iteration-i products ----
        __syncthreads();
        if (tid == 0) stRel(&g_flagF[i * 128 + d * 64 + slice]);
    }
}

__global__ void zero_flags() {
    int i = blockIdx.x * 256 + threadIdx.x;
    if (i < (TT + 2) * 128) g_flagF[i] = 0;
}

__global__ void enc_avg() {
    size_t i = (size_t)blockIdx.x * blockDim.x + threadIdx.x;
    if (i < (size_t)TBT * UU)
        g_enc[i] = 0.5f * (g_hall1[i] + g_hall1[(size_t)TBT * UU + i]);
}

// ---------------- attention scores ----------------
__global__ __launch_bounds__(256) void att_scores(
    const float* __restrict__ Wa0, const float* __restrict__ ba0,
    const float* __restrict__ alpha_a, const float* __restrict__ Wa1,
    const float* __restrict__ ba1)
{
    const int b = blockIdx.x;
    const int t0 = blockIdx.y * 16;
    __shared__ float encsT[512][16];
    __shared__ float red[256];
    const int tid = threadIdx.x;

    for (int i = tid; i < 16 * 512; i += 256) {
        int tt = i >> 9, u = i & 511;
        encsT[u][tt] = g_enc[((size_t)b * TT + t0 + tt) * UU + u];
    }
    __syncthreads();

    float a[16];
    float bb = ba0[tid];
    #pragma unroll
    for (int q = 0; q < 16; q++) a[q] = bb;

    for (int u = 0; u < 512; u++) {
        float w = Wa0[u * 256 + tid];
        const float4* row = (const float4*)encsT[u];
        float4 e0 = row[0], e1 = row[1], e2 = row[2], e3 = row[3];
        a[0]  += e0.x * w; a[1]  += e0.y * w; a[2]  += e0.z * w; a[3]  += e0.w * w;
        a[4]  += e1.x * w; a[5]  += e1.y * w; a[6]  += e1.z * w; a[7]  += e1.w * w;
        a[8]  += e2.x * w; a[9]  += e2.y * w; a[10] += e2.z * w; a[11] += e2.w * w;
        a[12] += e3.x * w; a[13] += e3.y * w; a[14] += e3.z * w; a[15] += e3.w * w;
    }

    float al = alpha_a[tid], w1 = Wa1[tid], b1v = ba1[0];
    for (int q = 0; q < 16; q++) {
        float v = a[q];
        v = (v >= 0.f) ? v : al * v;
        v *= w1;
        red[tid] = v; __syncthreads();
        for (int s = 128; s > 0; s >>= 1) {
            if (tid < s) red[tid] += red[tid + s];
            __syncthreads();
        }
        if (tid == 0) g_scores[b * TT + t0 + q] = red[0] + b1v;
        __syncthreads();
    }
}

// ---------------- softmax over T + weighted pooling ----------------
__global__ __launch_bounds__(256) void softmax_pool() {
    const int b = blockIdx.x;
    const int tid = threadIdx.x;
    __shared__ float ws[256];
    __shared__ float red[256];

    float s = g_scores[b * TT + tid];
    red[tid] = s; __syncthreads();
    for (int st = 128; st > 0; st >>= 1) {
        if (tid < st) red[tid] = fmaxf(red[tid], red[tid + st]);
        __syncthreads();
    }
    float mx = red[0]; __syncthreads();
    float e = expf(s - mx);
    red[tid] = e; __syncthreads();
    for (int st = 128; st > 0; st >>= 1) {
        if (tid < st) red[tid] += red[tid + st];
        __syncthreads();
    }
    float sum = red[0]; __syncthreads();
    ws[tid] = e / sum;
    __syncthreads();

    for (int u = tid; u < UU; u += 256) {
        float acc = 0.f;
        for (int t = 0; t < TT; t++)
            acc += g_enc[((size_t)b * TT + t) * UU + u] * ws[t];
        g_pooled[b * UU + u] = acc;
    }
}

// ---------------- classification head ----------------
__global__ __launch_bounds__(256) void head(
    const float* __restrict__ Wd0, const float* __restrict__ bd0,
    const float* __restrict__ gamma, const float* __restrict__ beta,
    const float* __restrict__ bnm, const float* __restrict__ bnv,
    const float* __restrict__ alpha_h, const float* __restrict__ Wd1,
    const float* __restrict__ bd1, float* __restrict__ out)
{
    const int b = blockIdx.x, j = threadIdx.x;
    __shared__ float ps[512];
    __shared__ float hs[256];
    __shared__ float lgs[7];

    for (int u = j; u < 512; u += 256) ps[u] = g_pooled[b * UU + u];
    __syncthreads();

    float h = bd0[j];
    for (int u = 0; u < 512; u++) h += ps[u] * Wd0[u * 256 + j];
    h = (h - bnm[j]) * rsqrtf(bnv[j] + 1e-3f) * gamma[j] + beta[j];
    h = (h >= 0.f) ? h : alpha_h[j] * h;
    hs[j] = h;
    __syncthreads();

    if (j < 7) {
        float lg = bd1[j];
        for (int k = 0; k < 256; k++) lg += hs[k] * Wd1[k * 7 + j];
        lgs[j] = lg;
    }
    __syncthreads();
    if (j == 0) {
        float mx = lgs[0];
        for (int l = 1; l < 7; l++) mx = fmaxf(mx, lgs[l]);
        float sum = 0.f, e[7];
        for (int l = 0; l < 7; l++) { e[l] = expf(lgs[l] - mx); sum += e[l]; }
        for (int l = 0; l < 7; l++) out[b * 7 + l] = e[l] / sum;
    }
}

// ---------------- driver ----------------
extern "C" void kernel_launch(void* const* d_in, const int* in_sizes, int n_in,
                              void* d_out, int out_size)
{
    const int*   ids   = (const int*)  d_in[0];
    const float* emb   = (const float*)d_in[1];
    const float* k0    = (const float*)d_in[2];
    const float* k12   = (const float*)d_in[3];
    const float* rec   = (const float*)d_in[4];
    const float* bias  = (const float*)d_in[5];
    const float* Wa0   = (const float*)d_in[6];
    const float* ba0   = (const float*)d_in[7];
    const float* al_a  = (const float*)d_in[8];
    const float* Wa1   = (const float*)d_in[9];
    const float* ba1   = (const float*)d_in[10];
    const float* Wd0   = (const float*)d_in[11];
    const float* bd0   = (const float*)d_in[12];
    const float* gamma = (const float*)d_in[13];
    const float* beta  = (const float*)d_in[14];
    const float* bnm   = (const float*)d_in[15];
    const float* bnv   = (const float*)d_in[16];
    const float* al_h  = (const float*)d_in[17];
    const float* Wd1   = (const float*)d_in[18];
    const float* bd1   = (const float*)d_in[19];
    float* out = (float*)d_out;

    cudaFuncSetAttribute((const void*)fused_lstm,
                         cudaFuncAttributeMaxDynamicSharedMemorySize, FUSED_SMEM_BYTES);

    dim3 ggrid(M2 / 128, GG / 64);   // (256, 32)

    gemm_mma<<<ggrid, 256>>>(ids, emb, k0, (long)EE * GG, bias, (long)3 * GG, EE);
    zero_flags<<<130, 256>>>();
    fused_lstm<<<128, 256, FUSED_SMEM_BYTES>>>(rec, k12, bias);

    enc_avg<<<(int)(((size_t)TBT * UU + 255) / 256), 256>>>();
    att_scores<<<dim3(BB, TT / 16), 256>>>(Wa0, ba0, al_a, Wa1, ba1);
    softmax_pool<<<BB, 256>>>();
    head<<<BB, 256>>>(Wd0, bd0, gamma, beta, bnm, bnv, al_h, Wd1, bd1, out);
}

// round 11
// speedup vs baseline: 3.1031x; 1.5793x over previous
#include <cuda_runtime.h>
#include <cuda_bf16.h>
#include <math.h>
#include <stdint.h>

#define BB 64
#define TT 256
#define EE 300
#define UU 512
#define GG 2048
#define TBT (BB*TT)     /* 16384 rows per direction */
#define M2  (2*TBT)     /* 32768 total rows */

// ---------------- device scratch (static allocation only) ----------------
__device__ float g_z[(size_t)M2 * GG];            // [2][B][T][4U] (layer-0 input proj)
__device__ float g_hall1[(size_t)2 * TBT * UU];   // [2][B][T][U]  final-layer h (fp32)
__device__ float g_enc[(size_t)TBT * UU];         // [B][T][U]
__device__ float g_scores[TBT];                   // [B][T]
__device__ float g_pooled[BB * UU];               // [B][U]
__device__ int g_flagF[(TT + 2) * 128];           // [iter][dir*64+slice]
// full-T bf16 A-fragment rings: [dir][t][mt][4096] u32
__device__ uint32_t g_ring1[(size_t)2 * TT * 4 * 4096];   // h1 (layer0 out)
__device__ uint32_t g_ring2[(size_t)2 * TT * 4 * 4096];   // h2 (layer1 out)
__device__ uint32_t g_ring3[(size_t)2 * TT * 4 * 4096];   // h3 (layer2 out)

__device__ __forceinline__ float sigf(float x) { return 1.f / (1.f + __expf(-x)); }
__device__ __forceinline__ float ssf(float x)  { return x / (1.f + fabsf(x)); }

__device__ __forceinline__ float to_tf32(float x) {
    uint32_t u; asm("cvt.rna.tf32.f32 %0, %1;" : "=r"(u) : "f"(x));
    return __uint_as_float(u);
}
__device__ __forceinline__ uint32_t fu(float x) { return __float_as_uint(x); }

__device__ __forceinline__ void stRel(int* p) {
    asm volatile("st.release.gpu.global.s32 [%0], %1;" :: "l"(p), "r"(1) : "memory");
}
__device__ __forceinline__ int acqLd(const int* p) {
    int v; asm volatile("ld.acquire.gpu.global.s32 %0, [%1];" : "=r"(v) : "l"(p) : "memory");
    return v;
}

#define MMA_TF32(d0,d1,d2,d3,a0,a1,a2,a3,b0,b1) \
    asm volatile("mma.sync.aligned.m16n8k8.row.col.f32.tf32.tf32.f32 " \
        "{%0,%1,%2,%3}, {%4,%5,%6,%7}, {%8,%9}, {%0,%1,%2,%3};" \
        : "+f"(d0), "+f"(d1), "+f"(d2), "+f"(d3) \
        : "r"(a0), "r"(a1), "r"(a2), "r"(a3), "r"(b0), "r"(b1))

#define MMA_BF16(d0,d1,d2,d3,a0,a1,a2,a3,b0,b1) \
    asm volatile("mma.sync.aligned.m16n8k16.row.col.f32.bf16.bf16.f32 " \
        "{%0,%1,%2,%3}, {%4,%5,%6,%7}, {%8,%9}, {%0,%1,%2,%3};" \
        : "+f"(d0), "+f"(d1), "+f"(d2), "+f"(d3) \
        : "r"(a0), "r"(a1), "r"(a2), "r"(a3), "r"(b0), "r"(b1))

// ================= big GEMM (layer-0 input proj): g_z = emb[ids] @ k0 + bias ====
__global__ __launch_bounds__(256) void gemm_mma(
    const int* __restrict__ ids, const float* __restrict__ emb,
    const float* __restrict__ Bbase, long Bstride,
    const float* __restrict__ biasBase, long biasStride, int K)
{
    __shared__ float As[128 * 36];
    __shared__ float Bs[32 * 72];
    __shared__ const float* rowp[128];

    const int m0 = blockIdx.x * 128;
    const int n0 = blockIdx.y * 64;
    const int d  = m0 / TBT;
    const float* Bmat = Bbase + (long)d * Bstride;
    const float* bias = biasBase + (long)d * biasStride;
    const int tid = threadIdx.x;

    if (tid < 128) {
        int m = m0 + tid;
        int bt = m % TBT;
        int b = bt / TT, t = bt % TT;
        int tt = d ? (TT - 1 - t) : t;
        rowp[tid] = emb + (long)ids[b * TT + tt] * EE;
    }
    __syncthreads();

    const int w = tid >> 5, lane = tid & 31;
    const int g = lane >> 2, t4 = lane & 3;
    const int mw = (w >> 1) * 32;
    const int nw = (w & 1) * 32;

    float acc[2][4][4];
    #pragma unroll
    for (int a = 0; a < 2; a++)
        #pragma unroll
        for (int b = 0; b < 4; b++)
            #pragma unroll
            for (int c = 0; c < 4; c++) acc[a][b][c] = 0.f;

    float4 aP[4], bP[2];
    const int nch = (K + 31) >> 5;

    auto ldA = [&](int kb) {
        bool full = (kb + 32) <= K;
        #pragma unroll
        for (int i = 0; i < 4; i++) {
            int idx = tid + i * 256;
            int row = idx >> 3, c4 = idx & 7;
            if (full) {
                aP[i] = *(const float4*)(rowp[row] + kb + c4 * 4);
            } else {
                float v[4];
                #pragma unroll
                for (int q = 0; q < 4; q++) {
                    int k = kb + c4 * 4 + q;
                    v[q] = (k < K) ? rowp[row][k] : 0.f;
                }
                aP[i] = make_float4(v[0], v[1], v[2], v[3]);
            }
        }
    };
    auto ldB = [&](int kb) {
        #pragma unroll
        for (int i = 0; i < 2; i++) {
            int idx = tid + i * 256;
            int kr = idx >> 4, c4 = idx & 15;
            int k = kb + kr;
            if (k < K) bP[i] = *(const float4*)(Bmat + (long)k * GG + n0 + c4 * 4);
            else       bP[i] = make_float4(0.f, 0.f, 0.f, 0.f);
        }
    };

    ldA(0); ldB(0);

    for (int c = 0; c < nch; c++) {
        __syncthreads();
        #pragma unroll
        for (int i = 0; i < 4; i++) {
            int idx = tid + i * 256;
            int row = idx >> 3, c4 = idx & 7;
            float4 v = aP[i];
            *(float4*)&As[row * 36 + c4 * 4] =
                make_float4(to_tf32(v.x), to_tf32(v.y), to_tf32(v.z), to_tf32(v.w));
        }
        #pragma unroll
        for (int i = 0; i < 2; i++) {
            int idx = tid + i * 256;
            int kr = idx >> 4, c4 = idx & 15;
            float4 v = bP[i];
            *(float4*)&Bs[kr * 72 + c4 * 4] =
                make_float4(to_tf32(v.x), to_tf32(v.y), to_tf32(v.z), to_tf32(v.w));
        }
        __syncthreads();
        if (c + 1 < nch) { ldA((c + 1) * 32); ldB((c + 1) * 32); }

        #pragma unroll
        for (int kk = 0; kk < 32; kk += 8) {
            uint32_t a[2][4];
            #pragma unroll
            for (int mt = 0; mt < 2; mt++) {
                int rb = mw + mt * 16;
                a[mt][0] = fu(As[(rb + g)     * 36 + kk + t4]);
                a[mt][1] = fu(As[(rb + 8 + g) * 36 + kk + t4]);
                a[mt][2] = fu(As[(rb + g)     * 36 + kk + t4 + 4]);
                a[mt][3] = fu(As[(rb + 8 + g) * 36 + kk + t4 + 4]);
            }
            #pragma unroll
            for (int nt = 0; nt < 4; nt++) {
                uint32_t b0 = fu(Bs[(kk + t4)     * 72 + nw + nt * 8 + g]);
                uint32_t b1 = fu(Bs[(kk + t4 + 4) * 72 + nw + nt * 8 + g]);
                MMA_TF32(acc[0][nt][0], acc[0][nt][1], acc[0][nt][2], acc[0][nt][3],
                         a[0][0], a[0][1], a[0][2], a[0][3], b0, b1);
                MMA_TF32(acc[1][nt][0], acc[1][nt][1], acc[1][nt][2], acc[1][nt][3],
                         a[1][0], a[1][1], a[1][2], a[1][3], b0, b1);
            }
        }
    }

    #pragma unroll
    for (int mt = 0; mt < 2; mt++) {
        #pragma unroll
        for (int nt = 0; nt < 4; nt++) {
            int col = n0 + nw + nt * 8 + 2 * t4;
            float b0 = bias[col], b1 = bias[col + 1];
            long r0 = (long)m0 + mw + mt * 16 + g;
            *(float2*)&g_z[r0 * GG + col] =
                make_float2(acc[mt][nt][0] + b0, acc[mt][nt][1] + b1);
            *(float2*)&g_z[(r0 + 8) * GG + col] =
                make_float2(acc[mt][nt][2] + b0, acc[mt][nt][3] + b1);
        }
    }
}

// ---- stage a 512x32-gate-col weight slice as bf16 B-fragments ----
__device__ __forceinline__ void stage_wfrags32(
    uint32_t* dstW, const float* W, int u0, int tid, int nthr)
{
    for (int i = tid; i < 32 * 4 * 32; i += nthr) {
        int cc = i >> 7;
        int nt = (i >> 5) & 3;
        int lane = i & 31;
        int gq = lane >> 2, t4 = lane & 3;
        int col = nt * 8 + gq;                 // gate = col>>3, unit = col&7
        long wcol = (long)(col >> 3) * UU + u0 + (col & 7);
        int k0 = cc * 16 + 2 * t4;
        __nv_bfloat162 b0, b1;
        b0.x = __float2bfloat16_rn(W[(long)k0 * GG + wcol]);
        b0.y = __float2bfloat16_rn(W[(long)(k0 + 1) * GG + wcol]);
        b1.x = __float2bfloat16_rn(W[(long)(k0 + 8) * GG + wcol]);
        b1.y = __float2bfloat16_rn(W[(long)(k0 + 9) * GG + wcol]);
        uint32_t* dst = dstW + (((cc * 2 + (nt >> 1)) * 32 + lane) << 2) + (nt & 1) * 2;
        dst[0] = *(uint32_t*)&b0;
        dst[1] = *(uint32_t*)&b1;
    }
}

// ---- one bf16 mma stream, full 32 cols per warp: acc[4][4] += A @ B ----
__device__ __forceinline__ void mma_stream4(
    float acc[4][4], const uint32_t* ring, const uint32_t* Ws, int lane)
{
    const uint4* r = (const uint4*)ring;
    uint4 buf[8];
    #pragma unroll
    for (int i = 0; i < 8; i++) buf[i] = r[i * 32 + lane];
    #pragma unroll
    for (int cc = 0; cc < 32; cc++) {
        uint4 av = buf[cc & 7];
        if (cc + 8 < 32) buf[cc & 7] = r[(cc + 8) * 32 + lane];
        uint4 b0 = *(const uint4*)&Ws[((cc * 2 + 0) * 32 + lane) << 2];
        uint4 b1 = *(const uint4*)&Ws[((cc * 2 + 1) * 32 + lane) << 2];
        MMA_BF16(acc[0][0], acc[0][1], acc[0][2], acc[0][3],
                 av.x, av.y, av.z, av.w, b0.x, b0.y);
        MMA_BF16(acc[1][0], acc[1][1], acc[1][2], acc[1][3],
                 av.x, av.y, av.z, av.w, b0.z, b0.w);
        MMA_BF16(acc[2][0], acc[2][1], acc[2][2], acc[2][3],
                 av.x, av.y, av.z, av.w, b1.x, b1.y);
        MMA_BF16(acc[3][0], acc[3][1], acc[3][2], acc[3][3],
                 av.x, av.y, av.z, av.w, b1.z, b1.w);
    }
}

// ============ fully-fused 3-layer bidirectional LSTM, warp-specialized ============
// 128 blocks: d = bx>>6, slice = bx&63 -> 8 units for ALL 3 layers.
// 384 threads = 12 warps = 3 stage-groups x 4 warps; each group owns one layer,
// so the three layers' load/mma chains overlap. One flag wave per iteration.
#define FUSED_SMEM_BYTES (163840 + 3*64*36*4)

__global__ __launch_bounds__(384) void fused_lstm(
    const float* __restrict__ recBase, const float* __restrict__ k12Base,
    const float* __restrict__ biasBase)
{
    extern __shared__ char smraw[];
    uint32_t* Ws0  = (uint32_t*)smraw;         // rec layer0
    uint32_t* Ws1k = Ws0 + 8192;               // k12 layer1
    uint32_t* Ws1r = Ws0 + 16384;              // rec layer1
    uint32_t* Ws2k = Ws0 + 24576;              // k12 layer2
    uint32_t* Ws2r = Ws0 + 32768;              // rec layer2
    float*    Cs   = (float*)(smraw + 163840); // [3][64][36]

    const int bx = blockIdx.x;
    const int d     = bx >> 6;
    const int slice = bx & 63;
    const int u0    = slice * 8;
    const int tid = threadIdx.x;

    stage_wfrags32(Ws0,  recBase + ((long)d * 3 + 0) * UU * GG, u0, tid, 384);
    stage_wfrags32(Ws1k, k12Base + ((long)d * 2 + 0) * UU * GG, u0, tid, 384);
    stage_wfrags32(Ws1r, recBase + ((long)d * 3 + 1) * UU * GG, u0, tid, 384);
    stage_wfrags32(Ws2k, k12Base + ((long)d * 2 + 1) * UU * GG, u0, tid, 384);
    stage_wfrags32(Ws2r, recBase + ((long)d * 3 + 2) * UU * GG, u0, tid, 384);
    __syncthreads();

    const int lane = tid & 31;
    const int wid  = tid >> 5;
    const int sg   = wid >> 2;        // stage group 0..2
    const int wi   = wid & 3;         // m-tile within group

    // epilogue mapping within group: 128 threads, 4 h-values each
    const int gtid = tid & 127;
    const int be = gtid >> 1;         // batch row 0..63
    const int uq = gtid & 1;          // unit quad: units u0..+3 or u0+4..+7 (of 8)
    const int mtE = be >> 4;
    // ring scatter (R9-validated, up = uq*2): two u32 stores at sIdx, sIdx+4
    const int sIdx = ((slice >> 1) * 32 + (be & 7) * 4 + uq * 2) * 4
                     + ((be >> 3) & 1) + 2 * (slice & 1);

    // per-group bias registers (layer sg; layer0 bias folded into g_z)
    float4 bg[4];
    if (sg > 0) {
        const float* bp = biasBase + ((long)d * 3 + sg) * GG;
        #pragma unroll
        for (int gate = 0; gate < 4; gate++)
            bg[gate] = *(const float4*)&bp[gate * UU + u0 + uq * 4];
    }

    float* CsS = Cs + sg * 2304;
    float4 cell = make_float4(0.f, 0.f, 0.f, 0.f);

    for (int i = 0; i < TT + 2; i++) {
        const bool s0 = (i < TT);
        const bool s1 = (i >= 1 && i <= TT);
        const bool s2 = (i >= 2);
        const int t0 = i, t1 = i - 1, t2 = i - 2;
        const bool act = (sg == 0) ? s0 : ((sg == 1) ? s1 : s2);
        const int ts = (sg == 0) ? t0 : ((sg == 1) ? t1 : t2);

        // ---- stage-0 z prefetch (flag-independent) ----
        float4 z0[4];
        if (sg == 0 && s0) {
            long zb = ((long)d * TBT + (long)be * TT + t0) * GG + u0 + uq * 4;
            #pragma unroll
            for (int gate = 0; gate < 4; gate++)
                z0[gate] = *(const float4*)&g_z[zb + gate * UU];
        }

        // ---- single wait: all same-dir blocks' iteration i-1 flags ----
        if (i > 0) {
            if (tid < 64) {
                const int* p = &g_flagF[(i - 1) * 128 + d * 64 + tid];
                while (acqLd(p) == 0) { }
            }
            __syncthreads();
        }

        // ---- per-group mma ----
        float acc[4][4];
        #pragma unroll
        for (int q = 0; q < 4; q++)
            #pragma unroll
            for (int r = 0; r < 4; r++) acc[q][r] = 0.f;

        if (sg == 0) {
            if (s0 && t0 > 0)
                mma_stream4(acc, &g_ring1[((size_t)(d * TT + t0 - 1) * 4 + wi) * 4096],
                            Ws0, lane);
        } else if (sg == 1) {
            if (s1) {
                mma_stream4(acc, &g_ring1[((size_t)(d * TT + t1) * 4 + wi) * 4096],
                            Ws1k, lane);
                if (t1 > 0)
                    mma_stream4(acc, &g_ring2[((size_t)(d * TT + t1 - 1) * 4 + wi) * 4096],
                                Ws1r, lane);
            }
        } else {
            if (s2) {
                mma_stream4(acc, &g_ring2[((size_t)(d * TT + t2) * 4 + wi) * 4096],
                            Ws2k, lane);
                if (t2 > 0)
                    mma_stream4(acc, &g_ring3[((size_t)(d * TT + t2 - 1) * 4 + wi) * 4096],
                                Ws2r, lane);
            }
        }
        __syncthreads();   // protect previous iteration's Cs reads

        // ---- dump fragments ----
        if (act) {
            const int t4 = lane & 3, g = lane >> 2;
            const int rw = wi * 16 + g;
            #pragma unroll
            for (int q = 0; q < 4; q++) {
                int col = q * 8 + 2 * t4;
                *(float2*)&CsS[rw * 36 + col]       = make_float2(acc[q][0], acc[q][1]);
                *(float2*)&CsS[(rw + 8) * 36 + col] = make_float2(acc[q][2], acc[q][3]);
            }
        }
        __syncthreads();

        // ---- per-group epilogue: 4 h-values per thread ----
        if (act) {
            float4 ci = *(const float4*)&CsS[be * 36 +  0 + uq * 4];
            float4 cf = *(const float4*)&CsS[be * 36 +  8 + uq * 4];
            float4 cg = *(const float4*)&CsS[be * 36 + 16 + uq * 4];
            float4 co = *(const float4*)&CsS[be * 36 + 24 + uq * 4];
            float4 zi4, zf4, zg4, zo4;
            if (sg == 0) { zi4 = z0[0]; zf4 = z0[1]; zg4 = z0[2]; zo4 = z0[3]; }
            else         { zi4 = bg[0]; zf4 = bg[1]; zg4 = bg[2]; zo4 = bg[3]; }
            float4 cn, hn;
            cn.x = sigf(cf.x + zf4.x) * cell.x + sigf(ci.x + zi4.x) * ssf(cg.x + zg4.x);
            cn.y = sigf(cf.y + zf4.y) * cell.y + sigf(ci.y + zi4.y) * ssf(cg.y + zg4.y);
            cn.z = sigf(cf.z + zf4.z) * cell.z + sigf(ci.z + zi4.z) * ssf(cg.z + zg4.z);
            cn.w = sigf(cf.w + zf4.w) * cell.w + sigf(ci.w + zi4.w) * ssf(cg.w + zg4.w);
            hn.x = sigf(co.x + zo4.x) * ssf(cn.x);
            hn.y = sigf(co.y + zo4.y) * ssf(cn.y);
            hn.z = sigf(co.z + zo4.z) * ssf(cn.z);
            hn.w = sigf(co.w + zo4.w) * ssf(cn.w);
            cell = cn;
            if (sg == 2)
                *(float4*)&g_hall1[((long)d * TBT + (long)be * TT + ts) * UU + u0 + uq * 4] = hn;
            __nv_bfloat162 p0, p1;
            p0.x = __float2bfloat16_rn(hn.x); p0.y = __float2bfloat16_rn(hn.y);
            p1.x = __float2bfloat16_rn(hn.z); p1.y = __float2bfloat16_rn(hn.w);
            uint32_t* ringOut = (sg == 0) ? g_ring1 : ((sg == 1) ? g_ring2 : g_ring3);
            uint32_t* rw = &ringOut[((size_t)(d * TT + ts) * 4 + mtE) * 4096 + sIdx];
            rw[0] = *(uint32_t*)&p0;
            rw[4] = *(uint32_t*)&p1;
        }

        // ---- signal this block's iteration-i products ----
        __syncthreads();
        if (tid == 0) stRel(&g_flagF[i * 128 + d * 64 + slice]);
    }
}

__global__ void zero_flags() {
    int i = blockIdx.x * 256 + threadIdx.x;
    if (i < (TT + 2) * 128) g_flagF[i] = 0;
}

__global__ void enc_avg() {
    size_t i = (size_t)blockIdx.x * blockDim.x + threadIdx.x;
    if (i < (size_t)TBT * UU)
        g_enc[i] = 0.5f * (g_hall1[i] + g_hall1[(size_t)TBT * UU + i]);
}

// ---------------- attention scores ----------------
__global__ __launch_bounds__(256) void att_scores(
    const float* __restrict__ Wa0, const float* __restrict__ ba0,
    const float* __restrict__ alpha_a, const float* __restrict__ Wa1,
    const float* __restrict__ ba1)
{
    const int b = blockIdx.x;
    const int t0 = blockIdx.y * 16;
    __shared__ float encsT[512][16];
    __shared__ float red[256];
    const int tid = threadIdx.x;

    for (int i = tid; i < 16 * 512; i += 256) {
        int tt = i >> 9, u = i & 511;
        encsT[u][tt] = g_enc[((size_t)b * TT + t0 + tt) * UU + u];
    }
    __syncthreads();

    float a[16];
    float bb = ba0[tid];
    #pragma unroll
    for (int q = 0; q < 16; q++) a[q] = bb;

    for (int u = 0; u < 512; u++) {
        float w = Wa0[u * 256 + tid];
        const float4* row = (const float4*)encsT[u];
        float4 e0 = row[0], e1 = row[1], e2 = row[2], e3 = row[3];
        a[0]  += e0.x * w; a[1]  += e0.y * w; a[2]  += e0.z * w; a[3]  += e0.w * w;
        a[4]  += e1.x * w; a[5]  += e1.y * w; a[6]  += e1.z * w; a[7]  += e1.w * w;
        a[8]  += e2.x * w; a[9]  += e2.y * w; a[10] += e2.z * w; a[11] += e2.w * w;
        a[12] += e3.x * w; a[13] += e3.y * w; a[14] += e3.z * w; a[15] += e3.w * w;
    }

    float al = alpha_a[tid], w1 = Wa1[tid], b1v = ba1[0];
    for (int q = 0; q < 16; q++) {
        float v = a[q];
        v = (v >= 0.f) ? v : al * v;
        v *= w1;
        red[tid] = v; __syncthreads();
        for (int s = 128; s > 0; s >>= 1) {
            if (tid < s) red[tid] += red[tid + s];
            __syncthreads();
        }
        if (tid == 0) g_scores[b * TT + t0 + q] = red[0] + b1v;
        __syncthreads();
    }
}

// ---------------- softmax over T + weighted pooling ----------------
__global__ __launch_bounds__(256) void softmax_pool() {
    const int b = blockIdx.x;
    const int tid = threadIdx.x;
    __shared__ float ws[256];
    __shared__ float red[256];

    float s = g_scores[b * TT + tid];
    red[tid] = s; __syncthreads();
    for (int st = 128; st > 0; st >>= 1) {
        if (tid < st) red[tid] = fmaxf(red[tid], red[tid + st]);
        __syncthreads();
    }
    float mx = red[0]; __syncthreads();
    float e = expf(s - mx);
    red[tid] = e; __syncthreads();
    for (int st = 128; st > 0; st >>= 1) {
        if (tid < st) red[tid] += red[tid + st];
        __syncthreads();
    }
    float sum = red[0]; __syncthreads();
    ws[tid] = e / sum;
    __syncthreads();

    for (int u = tid; u < UU; u += 256) {
        float acc = 0.f;
        for (int t = 0; t < TT; t++)
            acc += g_enc[((size_t)b * TT + t) * UU + u] * ws[t];
        g_pooled[b * UU + u] = acc;
    }
}

// ---------------- classification head ----------------
__global__ __launch_bounds__(256) void head(
    const float* __restrict__ Wd0, const float* __restrict__ bd0,
    const float* __restrict__ gamma, const float* __restrict__ beta,
    const float* __restrict__ bnm, const float* __restrict__ bnv,
    const float* __restrict__ alpha_h, const float* __restrict__ Wd1,
    const float* __restrict__ bd1, float* __restrict__ out)
{
    const int b = blockIdx.x, j = threadIdx.x;
    __shared__ float ps[512];
    __shared__ float hs[256];
    __shared__ float lgs[7];

    for (int u = j; u < 512; u += 256) ps[u] = g_pooled[b * UU + u];
    __syncthreads();

    float h = bd0[j];
    for (int u = 0; u < 512; u++) h += ps[u] * Wd0[u * 256 + j];
    h = (h - bnm[j]) * rsqrtf(bnv[j] + 1e-3f) * gamma[j] + beta[j];
    h = (h >= 0.f) ? h : alpha_h[j] * h;
    hs[j] = h;
    __syncthreads();

    if (j < 7) {
        float lg = bd1[j];
        for (int k = 0; k < 256; k++) lg += hs[k] * Wd1[k * 7 + j];
        lgs[j] = lg;
    }
    __syncthreads();
    if (j == 0) {
        float mx = lgs[0];
        for (int l = 1; l < 7; l++) mx = fmaxf(mx, lgs[l]);
        float sum = 0.f, e[7];
        for (int l = 0; l < 7; l++) { e[l] = expf(lgs[l] - mx); sum += e[l]; }
        for (int l = 0; l < 7; l++) out[b * 7 + l] = e[l] / sum;
    }
}

// ---------------- driver ----------------
extern "C" void kernel_launch(void* const* d_in, const int* in_sizes, int n_in,
                              void* d_out, int out_size)
{
    const int*   ids   = (const int*)  d_in[0];
    const float* emb   = (const float*)d_in[1];
    const float* k0    = (const float*)d_in[2];
    const float* k12   = (const float*)d_in[3];
    const float* rec   = (const float*)d_in[4];
    const float* bias  = (const float*)d_in[5];
    const float* Wa0   = (const float*)d_in[6];
    const float* ba0   = (const float*)d_in[7];
    const float* al_a  = (const float*)d_in[8];
    const float* Wa1   = (const float*)d_in[9];
    const float* ba1   = (const float*)d_in[10];
    const float* Wd0   = (const float*)d_in[11];
    const float* bd0   = (const float*)d_in[12];
    const float* gamma = (const float*)d_in[13];
    const float* beta  = (const float*)d_in[14];
    const float* bnm   = (const float*)d_in[15];
    const float* bnv   = (const float*)d_in[16];
    const float* al_h  = (const float*)d_in[17];
    const float* Wd1   = (const float*)d_in[18];
    const float* bd1   = (const float*)d_in[19];
    float* out = (float*)d_out;

    cudaFuncSetAttribute((const void*)fused_lstm,
                         cudaFuncAttributeMaxDynamicSharedMemorySize, FUSED_SMEM_BYTES);

    dim3 ggrid(M2 / 128, GG / 64);   // (256, 32)

    gemm_mma<<<ggrid, 256>>>(ids, emb, k0, (long)EE * GG, bias, (long)3 * GG, EE);
    zero_flags<<<130, 256>>>();
    fused_lstm<<<128, 384, FUSED_SMEM_BYTES>>>(rec, k12, bias);

    enc_avg<<<(int)(((size_t)TBT * UU + 255) / 256), 256>>>();
    att_scores<<<dim3(BB, TT / 16), 256>>>(Wa0, ba0, al_a, Wa1, ba1);
    softmax_pool<<<BB, 256>>>();
    head<<<BB, 256>>>(Wd0, bd0, gamma, beta, bnm, bnv, al_h, Wd1, bd1, out);
}

// round 12
// speedup vs baseline: 3.1144x; 1.0036x over previous
#include <cuda_runtime.h>
#include <cuda_bf16.h>
#include <math.h>
#include <stdint.h>

#define BB 64
#define TT 256
#define EE 300
#define UU 512
#define GG 2048
#define TBT (BB*TT)     /* 16384 rows per direction */
#define M2  (2*TBT)     /* 32768 total rows */

// ---------------- device scratch (static allocation only) ----------------
__device__ float g_z[(size_t)M2 * GG];            // [2][B][T][4U] (layer-0 input proj)
__device__ float g_hall1[(size_t)2 * TBT * UU];   // [2][B][T][U]  final-layer h (fp32)
__device__ float g_enc[(size_t)TBT * UU];         // [B][T][U]
__device__ float g_scores[TBT];                   // [B][T]
__device__ float g_pooled[BB * UU];               // [B][U]
__device__ int g_flagF[(TT + 2) * 128];           // [iter][dir*64+slice]
// full-T bf16 A-fragment rings: [dir][t][mt][4096] u32
__device__ uint32_t g_ring1[(size_t)2 * TT * 4 * 4096];   // h1 (layer0 out)
__device__ uint32_t g_ring2[(size_t)2 * TT * 4 * 4096];   // h2 (layer1 out)
__device__ uint32_t g_ring3[(size_t)2 * TT * 4 * 4096];   // h3 (layer2 out)

__device__ __forceinline__ float sigf(float x) { return 1.f / (1.f + __expf(-x)); }
__device__ __forceinline__ float ssf(float x)  { return x / (1.f + fabsf(x)); }

__device__ __forceinline__ float to_tf32(float x) {
    uint32_t u; asm("cvt.rna.tf32.f32 %0, %1;" : "=r"(u) : "f"(x));
    return __uint_as_float(u);
}
__device__ __forceinline__ uint32_t fu(float x) { return __float_as_uint(x); }

__device__ __forceinline__ void stRel(int* p) {
    asm volatile("st.release.gpu.global.s32 [%0], %1;" :: "l"(p), "r"(1) : "memory");
}
__device__ __forceinline__ int acqLd(const int* p) {
    int v; asm volatile("ld.acquire.gpu.global.s32 %0, [%1];" : "=r"(v) : "l"(p) : "memory");
    return v;
}

#define MMA_TF32(d0,d1,d2,d3,a0,a1,a2,a3,b0,b1) \
    asm volatile("mma.sync.aligned.m16n8k8.row.col.f32.tf32.tf32.f32 " \
        "{%0,%1,%2,%3}, {%4,%5,%6,%7}, {%8,%9}, {%0,%1,%2,%3};" \
        : "+f"(d0), "+f"(d1), "+f"(d2), "+f"(d3) \
        : "r"(a0), "r"(a1), "r"(a2), "r"(a3), "r"(b0), "r"(b1))

#define MMA_BF16(d0,d1,d2,d3,a0,a1,a2,a3,b0,b1) \
    asm volatile("mma.sync.aligned.m16n8k16.row.col.f32.bf16.bf16.f32 " \
        "{%0,%1,%2,%3}, {%4,%5,%6,%7}, {%8,%9}, {%0,%1,%2,%3};" \
        : "+f"(d0), "+f"(d1), "+f"(d2), "+f"(d3) \
        : "r"(a0), "r"(a1), "r"(a2), "r"(a3), "r"(b0), "r"(b1))

// ================= big GEMM (layer-0 input proj): g_z = emb[ids] @ k0 + bias ====
__global__ __launch_bounds__(256) void gemm_mma(
    const int* __restrict__ ids, const float* __restrict__ emb,
    const float* __restrict__ Bbase, long Bstride,
    const float* __restrict__ biasBase, long biasStride, int K)
{
    __shared__ float As[128 * 36];
    __shared__ float Bs[32 * 72];
    __shared__ const float* rowp[128];

    const int m0 = blockIdx.x * 128;
    const int n0 = blockIdx.y * 64;
    const int d  = m0 / TBT;
    const float* Bmat = Bbase + (long)d * Bstride;
    const float* bias = biasBase + (long)d * biasStride;
    const int tid = threadIdx.x;

    if (tid < 128) {
        int m = m0 + tid;
        int bt = m % TBT;
        int b = bt / TT, t = bt % TT;
        int tt = d ? (TT - 1 - t) : t;
        rowp[tid] = emb + (long)ids[b * TT + tt] * EE;
    }
    __syncthreads();

    const int w = tid >> 5, lane = tid & 31;
    const int g = lane >> 2, t4 = lane & 3;
    const int mw = (w >> 1) * 32;
    const int nw = (w & 1) * 32;

    float acc[2][4][4];
    #pragma unroll
    for (int a = 0; a < 2; a++)
        #pragma unroll
        for (int b = 0; b < 4; b++)
            #pragma unroll
            for (int c = 0; c < 4; c++) acc[a][b][c] = 0.f;

    float4 aP[4], bP[2];
    const int nch = (K + 31) >> 5;

    auto ldA = [&](int kb) {
        bool full = (kb + 32) <= K;
        #pragma unroll
        for (int i = 0; i < 4; i++) {
            int idx = tid + i * 256;
            int row = idx >> 3, c4 = idx & 7;
            if (full) {
                aP[i] = *(const float4*)(rowp[row] + kb + c4 * 4);
            } else {
                float v[4];
                #pragma unroll
                for (int q = 0; q < 4; q++) {
                    int k = kb + c4 * 4 + q;
                    v[q] = (k < K) ? rowp[row][k] : 0.f;
                }
                aP[i] = make_float4(v[0], v[1], v[2], v[3]);
            }
        }
    };
    auto ldB = [&](int kb) {
        #pragma unroll
        for (int i = 0; i < 2; i++) {
            int idx = tid + i * 256;
            int kr = idx >> 4, c4 = idx & 15;
            int k = kb + kr;
            if (k < K) bP[i] = *(const float4*)(Bmat + (long)k * GG + n0 + c4 * 4);
            else       bP[i] = make_float4(0.f, 0.f, 0.f, 0.f);
        }
    };

    ldA(0); ldB(0);

    for (int c = 0; c < nch; c++) {
        __syncthreads();
        #pragma unroll
        for (int i = 0; i < 4; i++) {
            int idx = tid + i * 256;
            int row = idx >> 3, c4 = idx & 7;
            float4 v = aP[i];
            *(float4*)&As[row * 36 + c4 * 4] =
                make_float4(to_tf32(v.x), to_tf32(v.y), to_tf32(v.z), to_tf32(v.w));
        }
        #pragma unroll
        for (int i = 0; i < 2; i++) {
            int idx = tid + i * 256;
            int kr = idx >> 4, c4 = idx & 15;
            float4 v = bP[i];
            *(float4*)&Bs[kr * 72 + c4 * 4] =
                make_float4(to_tf32(v.x), to_tf32(v.y), to_tf32(v.z), to_tf32(v.w));
        }
        __syncthreads();
        if (c + 1 < nch) { ldA((c + 1) * 32); ldB((c + 1) * 32); }

        #pragma unroll
        for (int kk = 0; kk < 32; kk += 8) {
            uint32_t a[2][4];
            #pragma unroll
            for (int mt = 0; mt < 2; mt++) {
                int rb = mw + mt * 16;
                a[mt][0] = fu(As[(rb + g)     * 36 + kk + t4]);
                a[mt][1] = fu(As[(rb + 8 + g) * 36 + kk + t4]);
                a[mt][2] = fu(As[(rb + g)     * 36 + kk + t4 + 4]);
                a[mt][3] = fu(As[(rb + 8 + g) * 36 + kk + t4 + 4]);
            }
            #pragma unroll
            for (int nt = 0; nt < 4; nt++) {
                uint32_t b0 = fu(Bs[(kk + t4)     * 72 + nw + nt * 8 + g]);
                uint32_t b1 = fu(Bs[(kk + t4 + 4) * 72 + nw + nt * 8 + g]);
                MMA_TF32(acc[0][nt][0], acc[0][nt][1], acc[0][nt][2], acc[0][nt][3],
                         a[0][0], a[0][1], a[0][2], a[0][3], b0, b1);
                MMA_TF32(acc[1][nt][0], acc[1][nt][1], acc[1][nt][2], acc[1][nt][3],
                         a[1][0], a[1][1], a[1][2], a[1][3], b0, b1);
            }
        }
    }

    #pragma unroll
    for (int mt = 0; mt < 2; mt++) {
        #pragma unroll
        for (int nt = 0; nt < 4; nt++) {
            int col = n0 + nw + nt * 8 + 2 * t4;
            float b0 = bias[col], b1 = bias[col + 1];
            long r0 = (long)m0 + mw + mt * 16 + g;
            *(float2*)&g_z[r0 * GG + col] =
                make_float2(acc[mt][nt][0] + b0, acc[mt][nt][1] + b1);
            *(float2*)&g_z[(r0 + 8) * GG + col] =
                make_float2(acc[mt][nt][2] + b0, acc[mt][nt][3] + b1);
        }
    }
}

// ---- stage a 512x32-gate-col weight slice as bf16 B-fragments ----
__device__ __forceinline__ void stage_wfrags32(
    uint32_t* dstW, const float* W, int u0, int tid, int nthr)
{
    for (int i = tid; i < 32 * 4 * 32; i += nthr) {
        int cc = i >> 7;
        int nt = (i >> 5) & 3;
        int lane = i & 31;
        int gq = lane >> 2, t4 = lane & 3;
        int col = nt * 8 + gq;                 // gate = col>>3, unit = col&7
        long wcol = (long)(col >> 3) * UU + u0 + (col & 7);
        int k0 = cc * 16 + 2 * t4;
        __nv_bfloat162 b0, b1;
        b0.x = __float2bfloat16_rn(W[(long)k0 * GG + wcol]);
        b0.y = __float2bfloat16_rn(W[(long)(k0 + 1) * GG + wcol]);
        b1.x = __float2bfloat16_rn(W[(long)(k0 + 8) * GG + wcol]);
        b1.y = __float2bfloat16_rn(W[(long)(k0 + 9) * GG + wcol]);
        uint32_t* dst = dstW + (((cc * 2 + (nt >> 1)) * 32 + lane) << 2) + (nt & 1) * 2;
        dst[0] = *(uint32_t*)&b0;
        dst[1] = *(uint32_t*)&b1;
    }
}

// ---- single bf16 mma stream, full 32 cols per warp ----
__device__ __forceinline__ void mma_stream4(
    float acc[4][4], const uint32_t* ring, const uint32_t* Ws, int lane)
{
    const uint4* r = (const uint4*)ring;
    uint4 buf[8];
    #pragma unroll
    for (int i = 0; i < 8; i++) buf[i] = r[i * 32 + lane];
    #pragma unroll
    for (int cc = 0; cc < 32; cc++) {
        uint4 av = buf[cc & 7];
        if (cc + 8 < 32) buf[cc & 7] = r[(cc + 8) * 32 + lane];
        uint4 b0 = *(const uint4*)&Ws[((cc * 2 + 0) * 32 + lane) << 2];
        uint4 b1 = *(const uint4*)&Ws[((cc * 2 + 1) * 32 + lane) << 2];
        MMA_BF16(acc[0][0], acc[0][1], acc[0][2], acc[0][3],
                 av.x, av.y, av.z, av.w, b0.x, b0.y);
        MMA_BF16(acc[1][0], acc[1][1], acc[1][2], acc[1][3],
                 av.x, av.y, av.z, av.w, b0.z, b0.w);
        MMA_BF16(acc[2][0], acc[2][1], acc[2][2], acc[2][3],
                 av.x, av.y, av.z, av.w, b1.x, b1.y);
        MMA_BF16(acc[3][0], acc[3][1], acc[3][2], acc[3][3],
                 av.x, av.y, av.z, av.w, b1.z, b1.w);
    }
}

// ---- dual interleaved streams: second ring's loads hide under first's MMAs ----
__device__ __forceinline__ void mma_dual(
    float acc[4][4],
    const uint32_t* ringA, const uint32_t* WsA,
    const uint32_t* ringB, const uint32_t* WsB, int lane)
{
    const uint4* rA = (const uint4*)ringA;
    const uint4* rB = (const uint4*)ringB;
    uint4 bufA[4], bufB[4];
    #pragma unroll
    for (int i = 0; i < 4; i++) { bufA[i] = rA[i * 32 + lane];
                                  bufB[i] = rB[i * 32 + lane]; }
    #pragma unroll
    for (int cc = 0; cc < 32; cc++) {
        uint4 av = bufA[cc & 3];
        uint4 bv = bufB[cc & 3];
        if (cc + 4 < 32) { bufA[cc & 3] = rA[(cc + 4) * 32 + lane];
                           bufB[cc & 3] = rB[(cc + 4) * 32 + lane]; }
        uint4 a0 = *(const uint4*)&WsA[((cc * 2 + 0) * 32 + lane) << 2];
        uint4 a1 = *(const uint4*)&WsA[((cc * 2 + 1) * 32 + lane) << 2];
        MMA_BF16(acc[0][0], acc[0][1], acc[0][2], acc[0][3],
                 av.x, av.y, av.z, av.w, a0.x, a0.y);
        MMA_BF16(acc[1][0], acc[1][1], acc[1][2], acc[1][3],
                 av.x, av.y, av.z, av.w, a0.z, a0.w);
        MMA_BF16(acc[2][0], acc[2][1], acc[2][2], acc[2][3],
                 av.x, av.y, av.z, av.w, a1.x, a1.y);
        MMA_BF16(acc[3][0], acc[3][1], acc[3][2], acc[3][3],
                 av.x, av.y, av.z, av.w, a1.z, a1.w);
        uint4 b0 = *(const uint4*)&WsB[((cc * 2 + 0) * 32 + lane) << 2];
        uint4 b1 = *(const uint4*)&WsB[((cc * 2 + 1) * 32 + lane) << 2];
        MMA_BF16(acc[0][0], acc[0][1], acc[0][2], acc[0][3],
                 bv.x, bv.y, bv.z, bv.w, b0.x, b0.y);
        MMA_BF16(acc[1][0], acc[1][1], acc[1][2], acc[1][3],
                 bv.x, bv.y, bv.z, bv.w, b0.z, b0.w);
        MMA_BF16(acc[2][0], acc[2][1], acc[2][2], acc[2][3],
                 bv.x, bv.y, bv.z, bv.w, b1.x, b1.y);
        MMA_BF16(acc[3][0], acc[3][1], acc[3][2], acc[3][3],
                 bv.x, bv.y, bv.z, bv.w, b1.z, b1.w);
    }
}

// ============ fused 3-layer bidir LSTM, warp-specialized, register epilogue =======
// Thread (wi, lane=(g,t4)) owns C rows {wi*16+g, +8} x units {2t4, 2t4+1}; gates
// are the n-tiles (q=gate). Epilogue is register-only; ring scatter: producer
// lane == consumer lane; cc = slice>>1; reg = (row>>3 &1) + 2*(slice&1).
#define FUSED_SMEM_BYTES 163840

__global__ __launch_bounds__(384) void fused_lstm(
    const float* __restrict__ recBase, const float* __restrict__ k12Base,
    const float* __restrict__ biasBase)
{
    extern __shared__ char smraw[];
    uint32_t* Ws0  = (uint32_t*)smraw;         // rec layer0
    uint32_t* Ws1k = Ws0 + 8192;               // k12 layer1
    uint32_t* Ws1r = Ws0 + 16384;              // rec layer1
    uint32_t* Ws2k = Ws0 + 24576;              // k12 layer2
    uint32_t* Ws2r = Ws0 + 32768;              // rec layer2

    const int bx = blockIdx.x;
    const int d     = bx >> 6;
    const int slice = bx & 63;
    const int u0    = slice * 8;
    const int tid = threadIdx.x;

    stage_wfrags32(Ws0,  recBase + ((long)d * 3 + 0) * UU * GG, u0, tid, 384);
    stage_wfrags32(Ws1k, k12Base + ((long)d * 2 + 0) * UU * GG, u0, tid, 384);
    stage_wfrags32(Ws1r, recBase + ((long)d * 3 + 1) * UU * GG, u0, tid, 384);
    stage_wfrags32(Ws2k, k12Base + ((long)d * 2 + 1) * UU * GG, u0, tid, 384);
    stage_wfrags32(Ws2r, recBase + ((long)d * 3 + 2) * UU * GG, u0, tid, 384);
    __syncthreads();

    const int lane = tid & 31;
    const int wid  = tid >> 5;
    const int sg   = wid >> 2;        // stage group 0..2
    const int wi   = wid & 3;         // m-tile within group
    const int g    = lane >> 2;
    const int t4   = lane & 3;

    const int R = wi * 16 + g;        // first owned batch row (second is R+8)
    // ring scatter slot: uint2 at [mt=wi] frag block
    const int ringSlot = (((slice >> 1) * 32 + lane) << 2) + 2 * (slice & 1);

    // bias add-terms (layers 1,2; layer-0 bias folded into g_z)
    float2 bg2[4];
    if (sg > 0) {
        const float* bp = biasBase + ((long)d * 3 + sg) * GG;
        #pragma unroll
        for (int q = 0; q < 4; q++)
            bg2[q] = *(const float2*)&bp[q * UU + u0 + 2 * t4];
    }

    uint32_t* ringOut = (sg == 0) ? g_ring1 : ((sg == 1) ? g_ring2 : g_ring3);

    float4 cell = make_float4(0.f, 0.f, 0.f, 0.f);

    for (int i = 0; i < TT + 2; i++) {
        const bool s0 = (i < TT);
        const bool s1 = (i >= 1 && i <= TT);
        const bool s2 = (i >= 2);
        const int t0 = i, t1 = i - 1, t2 = i - 2;
        const bool act = (sg == 0) ? s0 : ((sg == 1) ? s1 : s2);
        const int ts = (sg == 0) ? t0 : ((sg == 1) ? t1 : t2);

        // ---- stage-0 z prefetch (flag-independent): rows R, R+8 ----
        float2 zA[4], zB[4];
        if (sg == 0 && s0) {
            long zb = ((long)d * TBT + (long)R * TT + t0) * GG + u0 + 2 * t4;
            long zc = zb + (long)8 * TT * GG;
            #pragma unroll
            for (int q = 0; q < 4; q++) {
                zA[q] = *(const float2*)&g_z[zb + q * UU];
                zB[q] = *(const float2*)&g_z[zc + q * UU];
            }
        }

        // ---- single wait: all same-dir blocks' iteration i-1 flags ----
        if (i > 0) {
            if (tid < 64) {
                const int* p = &g_flagF[(i - 1) * 128 + d * 64 + tid];
                while (acqLd(p) == 0) { }
            }
            __syncthreads();
        }

        // ---- per-group mma (register-resident) ----
        float acc[4][4];
        #pragma unroll
        for (int q = 0; q < 4; q++)
            #pragma unroll
            for (int r = 0; r < 4; r++) acc[q][r] = 0.f;

        if (sg == 0) {
            if (s0 && t0 > 0)
                mma_stream4(acc, &g_ring1[((size_t)(d * TT + t0 - 1) * 4 + wi) * 4096],
                            Ws0, lane);
        } else if (sg == 1) {
            if (s1) {
                if (t1 > 0)
                    mma_dual(acc, &g_ring1[((size_t)(d * TT + t1) * 4 + wi) * 4096], Ws1k,
                             &g_ring2[((size_t)(d * TT + t1 - 1) * 4 + wi) * 4096], Ws1r,
                             lane);
                else
                    mma_stream4(acc, &g_ring1[((size_t)(d * TT + t1) * 4 + wi) * 4096],
                                Ws1k, lane);
            }
        } else {
            if (s2) {
                if (t2 > 0)
                    mma_dual(acc, &g_ring2[((size_t)(d * TT + t2) * 4 + wi) * 4096], Ws2k,
                             &g_ring3[((size_t)(d * TT + t2 - 1) * 4 + wi) * 4096], Ws2r,
                             lane);
                else
                    mma_stream4(acc, &g_ring2[((size_t)(d * TT + t2) * 4 + wi) * 4096],
                                Ws2k, lane);
            }
        }

        // ---- register epilogue: gates are n-tiles; 4 cells per thread ----
        if (act) {
            float2 aA[4], aB[4];
            if (sg == 0) {
                #pragma unroll
                for (int q = 0; q < 4; q++) { aA[q] = zA[q]; aB[q] = zB[q]; }
            } else {
                #pragma unroll
                for (int q = 0; q < 4; q++) { aA[q] = bg2[q]; aB[q] = bg2[q]; }
            }
            // row R: cells x,y ; row R+8: cells z,w
            float ci0 = acc[0][0] + aA[0].x, ci1 = acc[0][1] + aA[0].y;
            float cf0 = acc[1][0] + aA[1].x, cf1 = acc[1][1] + aA[1].y;
            float cg0 = acc[2][0] + aA[2].x, cg1 = acc[2][1] + aA[2].y;
            float co0 = acc[3][0] + aA[3].x, co1 = acc[3][1] + aA[3].y;
            float ci2 = acc[0][2] + aB[0].x, ci3 = acc[0][3] + aB[0].y;
            float cf2 = acc[1][2] + aB[1].x, cf3 = acc[1][3] + aB[1].y;
            float cg2v = acc[2][2] + aB[2].x, cg3 = acc[2][3] + aB[2].y;
            float co2 = acc[3][2] + aB[3].x, co3 = acc[3][3] + aB[3].y;

            cell.x = sigf(cf0) * cell.x + sigf(ci0) * ssf(cg0);
            cell.y = sigf(cf1) * cell.y + sigf(ci1) * ssf(cg1);
            cell.z = sigf(cf2) * cell.z + sigf(ci2) * ssf(cg2v);
            cell.w = sigf(cf3) * cell.w + sigf(ci3) * ssf(cg3);
            float h0 = sigf(co0) * ssf(cell.x);
            float h1 = sigf(co1) * ssf(cell.y);
            float h2 = sigf(co2) * ssf(cell.z);
            float h3 = sigf(co3) * ssf(cell.w);

            if (sg == 2) {
                long hb = ((long)d * TBT + (long)R * TT + ts) * UU + u0 + 2 * t4;
                *(float2*)&g_hall1[hb] = make_float2(h0, h1);
                *(float2*)&g_hall1[hb + (long)8 * TT * UU] = make_float2(h2, h3);
            }
            __nv_bfloat162 p0, p1;
            p0.x = __float2bfloat16_rn(h0); p0.y = __float2bfloat16_rn(h1);
            p1.x = __float2bfloat16_rn(h2); p1.y = __float2bfloat16_rn(h3);
            uint2 pk = make_uint2(*(uint32_t*)&p0, *(uint32_t*)&p1);
            *(uint2*)&ringOut[((size_t)(d * TT + ts) * 4 + wi) * 4096 + ringSlot] = pk;
        }

        // ---- signal this block's iteration-i products ----
        __syncthreads();
        if (tid == 0) stRel(&g_flagF[i * 128 + d * 64 + slice]);
    }
}

__global__ void zero_flags() {
    int i = blockIdx.x * 256 + threadIdx.x;
    if (i < (TT + 2) * 128) g_flagF[i] = 0;
}

__global__ void enc_avg() {
    size_t i = (size_t)blockIdx.x * blockDim.x + threadIdx.x;
    if (i < (size_t)TBT * UU)
        g_enc[i] = 0.5f * (g_hall1[i] + g_hall1[(size_t)TBT * UU + i]);
}

// ---------------- attention scores ----------------
__global__ __launch_bounds__(256) void att_scores(
    const float* __restrict__ Wa0, const float* __restrict__ ba0,
    const float* __restrict__ alpha_a, const float* __restrict__ Wa1,
    const float* __restrict__ ba1)
{
    const int b = blockIdx.x;
    const int t0 = blockIdx.y * 16;
    __shared__ float encsT[512][16];
    __shared__ float red[256];
    const int tid = threadIdx.x;

    for (int i = tid; i < 16 * 512; i += 256) {
        int tt = i >> 9, u = i & 511;
        encsT[u][tt] = g_enc[((size_t)b * TT + t0 + tt) * UU + u];
    }
    __syncthreads();

    float a[16];
    float bb = ba0[tid];
    #pragma unroll
    for (int q = 0; q < 16; q++) a[q] = bb;

    for (int u = 0; u < 512; u++) {
        float w = Wa0[u * 256 + tid];
        const float4* row = (const float4*)encsT[u];
        float4 e0 = row[0], e1 = row[1], e2 = row[2], e3 = row[3];
        a[0]  += e0.x * w; a[1]  += e0.y * w; a[2]  += e0.z * w; a[3]  += e0.w * w;
        a[4]  += e1.x * w; a[5]  += e1.y * w; a[6]  += e1.z * w; a[7]  += e1.w * w;
        a[8]  += e2.x * w; a[9]  += e2.y * w; a[10] += e2.z * w; a[11] += e2.w * w;
        a[12] += e3.x * w; a[13] += e3.y * w; a[14] += e3.z * w; a[15] += e3.w * w;
    }

    float al = alpha_a[tid], w1 = Wa1[tid], b1v = ba1[0];
    for (int q = 0; q < 16; q++) {
        float v = a[q];
        v = (v >= 0.f) ? v : al * v;
        v *= w1;
        red[tid] = v; __syncthreads();
        for (int s = 128; s > 0; s >>= 1) {
            if (tid < s) red[tid] += red[tid + s];
            __syncthreads();
        }
        if (tid == 0) g_scores[b * TT + t0 + q] = red[0] + b1v;
        __syncthreads();
    }
}

// ---------------- softmax over T + weighted pooling ----------------
__global__ __launch_bounds__(256) void softmax_pool() {
    const int b = blockIdx.x;
    const int tid = threadIdx.x;
    __shared__ float ws[256];
    __shared__ float red[256];

    float s = g_scores[b * TT + tid];
    red[tid] = s; __syncthreads();
    for (int st = 128; st > 0; st >>= 1) {
        if (tid < st) red[tid] = fmaxf(red[tid], red[tid + st]);
        __syncthreads();
    }
    float mx = red[0]; __syncthreads();
    float e = expf(s - mx);
    red[tid] = e; __syncthreads();
    for (int st = 128; st > 0; st >>= 1) {
        if (tid < st) red[tid] += red[tid + st];
        __syncthreads();
    }
    float sum = red[0]; __syncthreads();
    ws[tid] = e / sum;
    __syncthreads();

    for (int u = tid; u < UU; u += 256) {
        float acc = 0.f;
        for (int t = 0; t < TT; t++)
            acc += g_enc[((size_t)b * TT + t) * UU + u] * ws[t];
        g_pooled[b * UU + u] = acc;
    }
}

// ---------------- classification head ----------------
__global__ __launch_bounds__(256) void head(
    const float* __restrict__ Wd0, const float* __restrict__ bd0,
    const float* __restrict__ gamma, const float* __restrict__ beta,
    const float* __restrict__ bnm, const float* __restrict__ bnv,
    const float* __restrict__ alpha_h, const float* __restrict__ Wd1,
    const float* __restrict__ bd1, float* __restrict__ out)
{
    const int b = blockIdx.x, j = threadIdx.x;
    __shared__ float ps[512];
    __shared__ float hs[256];
    __shared__ float lgs[7];

    for (int u = j; u < 512; u += 256) ps[u] = g_pooled[b * UU + u];
    __syncthreads();

    float h = bd0[j];
    for (int u = 0; u < 512; u++) h += ps[u] * Wd0[u * 256 + j];
    h = (h - bnm[j]) * rsqrtf(bnv[j] + 1e-3f) * gamma[j] + beta[j];
    h = (h >= 0.f) ? h : alpha_h[j] * h;
    hs[j] = h;
    __syncthreads();

    if (j < 7) {
        float lg = bd1[j];
        for (int k = 0; k < 256; k++) lg += hs[k] * Wd1[k * 7 + j];
        lgs[j] = lg;
    }
    __syncthreads();
    if (j == 0) {
        float mx = lgs[0];
        for (int l = 1; l < 7; l++) mx = fmaxf(mx, lgs[l]);
        float sum = 0.f, e[7];
        for (int l = 0; l < 7; l++) { e[l] = expf(lgs[l] - mx); sum += e[l]; }
        for (int l = 0; l < 7; l++) out[b * 7 + l] = e[l] / sum;
    }
}

// ---------------- driver ----------------
extern "C" void kernel_launch(void* const* d_in, const int* in_sizes, int n_in,
                              void* d_out, int out_size)
{
    const int*   ids   = (const int*)  d_in[0];
    const float* emb   = (const float*)d_in[1];
    const float* k0    = (const float*)d_in[2];
    const float* k12   = (const float*)d_in[3];
    const float* rec   = (const float*)d_in[4];
    const float* bias  = (const float*)d_in[5];
    const float* Wa0   = (const float*)d_in[6];
    const float* ba0   = (const float*)d_in[7];
    const float* al_a  = (const float*)d_in[8];
    const float* Wa1   = (const float*)d_in[9];
    const float* ba1   = (const float*)d_in[10];
    const float* Wd0   = (const float*)d_in[11];
    const float* bd0   = (const float*)d_in[12];
    const float* gamma = (const float*)d_in[13];
    const float* beta  = (const float*)d_in[14];
    const float* bnm   = (const float*)d_in[15];
    const float* bnv   = (const float*)d_in[16];
    const float* al_h  = (const float*)d_in[17];
    const float* Wd1   = (const float*)d_in[18];
    const float* bd1   = (const float*)d_in[19];
    float* out = (float*)d_out;

    cudaFuncSetAttribute((const void*)fused_lstm,
                         cudaFuncAttributeMaxDynamicSharedMemorySize, FUSED_SMEM_BYTES);

    dim3 ggrid(M2 / 128, GG / 64);   // (256, 32)

    gemm_mma<<<ggrid, 256>>>(ids, emb, k0, (long)EE * GG, bias, (long)3 * GG, EE);
    zero_flags<<<130, 256>>>();
    fused_lstm<<<128, 384, FUSED_SMEM_BYTES>>>(rec, k12, bias);

    enc_avg<<<(int)(((size_t)TBT * UU + 255) / 256), 256>>>();
    att_scores<<<dim3(BB, TT / 16), 256>>>(Wa0, ba0, al_a, Wa1, ba1);
    softmax_pool<<<BB, 256>>>();
    head<<<BB, 256>>>(Wd0, bd0, gamma, beta, bnm, bnv, al_h, Wd1, bd1, out);
}